// round 13
// baseline (speedup 1.0000x reference)
#include <cuda_runtime.h>
#include <cuda_bf16.h>
#include <cstdint>
#include <math.h>

// ---------------- problem constants ----------------
#define N_DRUGS   4000
#define N_GENES   4264
#define NNODES    8264
#define IN_DIM    1613
#define DIM1      1340
#define DIM2      920
#define DIM3      740
#define N_REL     4
#define N_EDGES   100000
#define NSEG      (NNODES * N_REL)     // 33056

#define MPAD      8320                 // 65 * 128
#define KP1       1664                 // pad(1613, 64)
#define KP2       1344                 // pad(1340, 64)
#define KP3       960                  // pad(920, 64)
#define KC1       (5 * KP1)            // 8320
#define KC2       (5 * KP2)            // 6720
#define NP1       1408                 // 11 * 128
#define NP2       960                  // 15 * 64
#define NP3       768                  // 6 * 128

// ---------------- device scratch ----------------
__device__ __nv_bfloat16 g_Xcat_hi[(size_t)MPAD * KC1];
__device__ __nv_bfloat16 g_Xcat_lo[(size_t)MPAD * KC1];
__device__ __nv_bfloat16 g_W1hi[(size_t)NP1 * KC1];
__device__ __nv_bfloat16 g_W1lo[(size_t)NP1 * KC1];
__device__ float         g_A1[(size_t)NNODES * DIM1];
__device__ __nv_bfloat16 g_A1cat_hi[(size_t)MPAD * KC2];
__device__ __nv_bfloat16 g_A1cat_lo[(size_t)MPAD * KC2];
__device__ __nv_bfloat16 g_W2hi[(size_t)NP2 * KC2];
__device__ __nv_bfloat16 g_W2lo[(size_t)NP2 * KC2];
__device__ __nv_bfloat16 g_A2hi[(size_t)MPAD * KP3];
__device__ __nv_bfloat16 g_A2lo[(size_t)MPAD * KP3];
__device__ __nv_bfloat16 g_W3hi[(size_t)NP3 * KP3];
__device__ __nv_bfloat16 g_W3lo[(size_t)NP3 * KP3];
__device__ int g_cnt[NSEG];
__device__ int g_seg_start[NSEG + 1];
__device__ int g_cursor[NSEG];
__device__ int g_esrc[N_EDGES];

// ---------------- PTX helpers (plain sm_80+ instructions only) ----------------
__device__ __forceinline__ uint32_t smem_to_u32(const void* p) {
    uint32_t a;
    asm("{ .reg .u64 t; cvta.to.shared.u64 t, %1; cvt.u32.u64 %0, t; }" : "=r"(a) : "l"(p));
    return a;
}
#define CP_ASYNC16(dst, src) \
    asm volatile("cp.async.cg.shared.global [%0], [%1], 16;" :: "r"(dst), "l"(src) : "memory")
#define CP_ASYNC_COMMIT() asm volatile("cp.async.commit_group;" ::: "memory")
#define CP_ASYNC_WAIT(n)  asm volatile("cp.async.wait_group %0;" :: "n"(n) : "memory")

__device__ __forceinline__ void ldsm4(uint32_t (&r)[4], uint32_t addr) {
    asm volatile("ldmatrix.sync.aligned.m8n8.x4.shared.b16 {%0,%1,%2,%3}, [%4];"
                 : "=r"(r[0]), "=r"(r[1]), "=r"(r[2]), "=r"(r[3]) : "r"(addr));
}
__device__ __forceinline__ void mma16816(float (&d)[4], const uint32_t (&a)[4],
                                         uint32_t b0, uint32_t b1) {
    asm volatile(
        "mma.sync.aligned.m16n8k16.row.col.f32.bf16.bf16.f32 "
        "{%0,%1,%2,%3}, {%4,%5,%6,%7}, {%8,%9}, {%0,%1,%2,%3};"
        : "+f"(d[0]), "+f"(d[1]), "+f"(d[2]), "+f"(d[3])
        : "r"(a[0]), "r"(a[1]), "r"(a[2]), "r"(a[3]), "r"(b0), "r"(b1));
}
#define SWZ(off) ((off) ^ (((off) >> 3) & 0x70))

// ---------------- edge preprocessing ----------------
__global__ void zero_cnt_kernel()
{
    int i = blockIdx.x * blockDim.x + threadIdx.x;
    if (i < NSEG) g_cnt[i] = 0;
}
__global__ void count_kernel(const int* __restrict__ ei, const int* __restrict__ et)
{
    int e = blockIdx.x * blockDim.x + threadIdx.x;
    if (e >= N_EDGES) return;
    atomicAdd(&g_cnt[ei[N_EDGES + e] * N_REL + et[e]], 1);
}
__global__ void scan_kernel()
{
    __shared__ int part[1024];
    const int CHK = (NSEG + 1023) / 1024;
    int tid = threadIdx.x;
    int degs[CHK];
    int mysum = 0;
#pragma unroll
    for (int i = 0; i < CHK; i++) {
        int d = tid * CHK + i;
        int dg = (d < NSEG) ? g_cnt[d] : 0;
        degs[i] = dg;
        mysum += dg;
    }
    part[tid] = mysum;
    __syncthreads();
    if (tid == 0) {
        int run = 0;
        for (int t = 0; t < 1024; t++) { int v = part[t]; part[t] = run; run += v; }
        g_seg_start[NSEG] = run;
    }
    __syncthreads();
    int off = part[tid];
#pragma unroll
    for (int i = 0; i < CHK; i++) {
        int d = tid * CHK + i;
        if (d < NSEG) { g_seg_start[d] = off; g_cursor[d] = off; off += degs[i]; }
    }
}
__global__ void fill_kernel(const int* __restrict__ ei, const int* __restrict__ et)
{
    int e = blockIdx.x * blockDim.x + threadIdx.x;
    if (e >= N_EDGES) return;
    int seg = ei[N_EDGES + e] * N_REL + et[e];
    g_esrc[atomicAdd(&g_cursor[seg], 1)] = ei[e];
}

// ---------------- device bodies for fused prep ----------------
__device__ __forceinline__ void transpose_split_body(
    const float* __restrict__ Wrel, const float* __restrict__ Wroot,
    __nv_bfloat16* __restrict__ Thi, __nv_bfloat16* __restrict__ Tlo,
    int K, int N, int Kpad, int KC, int bx, int by, int bz, int tid,
    float (*t)[33])
{
    const float* W = (Wrel != nullptr && bz < N_REL) ? (Wrel + (size_t)bz * K * N) : Wroot;
    int k0 = bx * 32;
    int n0 = by * 32;
    int tx = tid & 31, ty = tid >> 5;
#pragma unroll
    for (int i = 0; i < 4; i++) {
        int k = k0 + ty + i * 8;
        int n = n0 + tx;
        t[ty + i * 8][tx] = (k < K && n < N) ? W[(size_t)k * N + n] : 0.f;
    }
    __syncthreads();
#pragma unroll
    for (int i = 0; i < 4; i++) {
        int n = n0 + ty + i * 8;
        int kk = k0 + tx;
        float v = t[tx][ty + i * 8];
        __nv_bfloat16 hi = __float2bfloat16(v);
        size_t o = (size_t)n * KC + (size_t)bz * Kpad + kk;
        Thi[o] = hi;
        Tlo[o] = __float2bfloat16(v - __bfloat162float(hi));
    }
}

template <int CH>
__device__ __forceinline__ void agg_seg_body(
    const float* __restrict__ src0, const float* __restrict__ src1,
    int splitRow, int D, int Kpad, int KC,
    __nv_bfloat16* __restrict__ outHi, __nv_bfloat16* __restrict__ outLo,
    int seg, int tid)
{
    int s = g_seg_start[seg];
    int e = g_seg_start[seg + 1];
    if (s == e) return;
    float acc[CH];
#pragma unroll
    for (int j = 0; j < CH; j++) acc[j] = 0.f;
    for (int p = s; p < e; p++) {
        int sn = g_esrc[p];
        const float* row = (sn < splitRow) ? (src0 + (size_t)sn * D)
                                           : (src1 + (size_t)(sn - splitRow) * D);
#pragma unroll
        for (int j = 0; j < CH; j++) {
            int o = tid + j * 256;
            if (o < D) acc[j] += row[o];
        }
    }
    float inv = 1.0f / (float)(e - s);
    int node = seg >> 2, rel = seg & 3;
    size_t base = (size_t)node * KC + (size_t)rel * Kpad;
#pragma unroll
    for (int j = 0; j < CH; j++) {
        int o = tid + j * 256;
        if (o < D) {
            float v = acc[j] * inv;
            __nv_bfloat16 hi = __float2bfloat16(v);
            outHi[base + o] = hi;
            outLo[base + o] = __float2bfloat16(v - __bfloat162float(hi));
        }
    }
}

// ---------------- fused prep: xfill + 3 weight transposes + layer-1 agg ----------------
#define GX_FUSED   (((size_t)NNODES * IN_DIM + 255) / 256)          // 52070
#define GT1_FUSED  ((KP1 / 32) * (NP1 / 32) * 5)                    // 52*44*5 = 11440
#define GT2_FUSED  ((KP2 / 32) * (NP2 / 32) * 5)                    // 42*30*5 = 6300
#define GT3_FUSED  ((KP3 / 32) * (NP3 / 32) * 1)                    // 30*24 = 720
#define GFUSED     ((int)GX_FUSED + GT1_FUSED + GT2_FUSED + GT3_FUSED + NSEG)

__global__ void __launch_bounds__(256)
fused_prep_kernel(const float* __restrict__ x, const float* __restrict__ gene,
                  const float* __restrict__ w_rel1, const float* __restrict__ root1,
                  const float* __restrict__ w_rel2, const float* __restrict__ root2,
                  const float* __restrict__ lin1_w)
{
    __shared__ float t[32][33];
    int bid = blockIdx.x;
    int tid = threadIdx.x;
    if (bid < (int)GX_FUSED) {
        // xfill: root slot of Xcat
        size_t i = (size_t)bid * 256 + tid;
        if (i < (size_t)NNODES * IN_DIM) {
            int node = (int)(i / IN_DIM);
            int k = (int)(i % IN_DIM);
            float v = (node < N_DRUGS) ? x[(size_t)node * IN_DIM + k]
                                       : gene[(size_t)(node - N_DRUGS) * IN_DIM + k];
            __nv_bfloat16 hi = __float2bfloat16(v);
            size_t o = (size_t)node * KC1 + 4 * KP1 + k;
            g_Xcat_hi[o] = hi;
            g_Xcat_lo[o] = __float2bfloat16(v - __bfloat162float(hi));
        }
        return;
    }
    bid -= (int)GX_FUSED;
    if (bid < GT1_FUSED) {
        int bx = bid % (KP1 / 32), r = bid / (KP1 / 32);
        int by = r % (NP1 / 32), bz = r / (NP1 / 32);
        transpose_split_body(w_rel1, root1, g_W1hi, g_W1lo, IN_DIM, DIM1, KP1, KC1, bx, by, bz, tid, t);
        return;
    }
    bid -= GT1_FUSED;
    if (bid < GT2_FUSED) {
        int bx = bid % (KP2 / 32), r = bid / (KP2 / 32);
        int by = r % (NP2 / 32), bz = r / (NP2 / 32);
        transpose_split_body(w_rel2, root2, g_W2hi, g_W2lo, DIM1, DIM2, KP2, KC2, bx, by, bz, tid, t);
        return;
    }
    bid -= GT2_FUSED;
    if (bid < GT3_FUSED) {
        int bx = bid % (KP3 / 32);
        int by = bid / (KP3 / 32);
        transpose_split_body(nullptr, lin1_w, g_W3hi, g_W3lo, DIM2, DIM3, KP3, KP3, bx, by, 0, tid, t);
        return;
    }
    bid -= GT3_FUSED;
    // layer-1 aggregation (reads x/gene, writes Xcat relation slots)
    agg_seg_body<7>(x, gene, N_DRUGS, IN_DIM, KP1, KC1, g_Xcat_hi, g_Xcat_lo, bid, tid);
}

// ---------------- standalone agg for layer 2 ----------------
template <int CH>
__global__ void agg_seg_kernel(const float* __restrict__ src0, const float* __restrict__ src1,
                               int splitRow, int D, int Kpad, int KC,
                               __nv_bfloat16* __restrict__ outHi, __nv_bfloat16* __restrict__ outLo)
{
    agg_seg_body<CH>(src0, src1, splitRow, D, Kpad, KC, outHi, outLo, blockIdx.x, threadIdx.x);
}

// ---------------- mma.sync bf16-split GEMM, templated on N tile ----------------
#define TILE_B  (128 * 128)          // A tile bytes
#define GTHREADS 512

template <int NBLK>
__global__ void __launch_bounds__(GTHREADS, 1)
gemm_mma_kernel(const __nv_bfloat16* __restrict__ Ahi, const __nv_bfloat16* __restrict__ Alo,
                const __nv_bfloat16* __restrict__ Bhi, const __nv_bfloat16* __restrict__ Blo,
                int KC, int Nout, const float* __restrict__ bias,
                float* __restrict__ outF,
                __nv_bfloat16* __restrict__ outHi, __nv_bfloat16* __restrict__ outLo,
                int strideO, int colOff)
{
    constexpr int BT_B = NBLK * 128;
    constexpr int STAGE_B = 2 * TILE_B + 2 * BT_B;
    constexpr int WN = NBLK / 4;
    constexpr int NR = WN / 16;
    constexpr int NT = WN / 8;
    constexpr int LOADS = (2048 + 16 * NBLK) / GTHREADS;

    extern __shared__ char dsm[];
    const uint32_t sbase = smem_to_u32(dsm);
    const int tid = threadIdx.x;
    const int lane = tid & 31;
    const int wid = tid >> 5;
    const int m_off = (wid >> 2) * 32;
    const int n_off = (wid & 3) * WN;
    const int m0 = blockIdx.y * 128;
    const int n0 = blockIdx.x * NBLK;

    const int arow = lane & 15;
    const uint32_t xorv = (uint32_t)(arow & 7) << 4;
    uint32_t colp[4];
#pragma unroll
    for (int ks = 0; ks < 4; ks++)
        colp[ks] = ((uint32_t)(ks * 32 + ((lane >> 4) * 16))) ^ xorv;
    uint32_t rowA[2], rowB[NR];
#pragma unroll
    for (int mi = 0; mi < 2; mi++) rowA[mi] = (uint32_t)(m_off + mi * 16 + arow) * 128u;
#pragma unroll
    for (int nj = 0; nj < NR; nj++) rowB[nj] = (uint32_t)(n_off + nj * 16 + arow) * 128u;

    float acc[2][NT][4];
#pragma unroll
    for (int mi = 0; mi < 2; mi++)
#pragma unroll
        for (int nt = 0; nt < NT; nt++)
#pragma unroll
            for (int q = 0; q < 4; q++) acc[mi][nt][q] = 0.f;

    const int chunks = KC >> 6;

    auto load_stage = [&](int slot, int c) {
        const int k0 = c << 6;
        const uint32_t base = sbase + (uint32_t)slot * STAGE_B;
#pragma unroll
        for (int i = 0; i < LOADS; i++) {
            int idx = tid + i * GTHREADS;
            const __nv_bfloat16* g;
            uint32_t d;
            if (idx < 2048) {
                int t = idx >> 10;
                int r = (idx >> 3) & 127, j = idx & 7;
                g = (t ? Alo : Ahi) + (size_t)(m0 + r) * KC + k0 + j * 8;
                d = base + (uint32_t)t * TILE_B + SWZ((uint32_t)(r * 128 + j * 16));
            } else {
                int i2 = idx - 2048;
                int t = i2 / (8 * NBLK);
                int r = (i2 >> 3) % NBLK, j = i2 & 7;
                g = (t ? Blo : Bhi) + (size_t)(n0 + r) * KC + k0 + j * 8;
                d = base + 2 * TILE_B + (uint32_t)t * BT_B + SWZ((uint32_t)(r * 128 + j * 16));
            }
            CP_ASYNC16(d, (const void*)g);
        }
        CP_ASYNC_COMMIT();
    };

    load_stage(0, 0);
    if (chunks > 1) load_stage(1, 1);

    for (int c = 0; c < chunks; c++) {
        if (c + 1 < chunks) CP_ASYNC_WAIT(1);
        else                CP_ASYNC_WAIT(0);
        __syncthreads();
        if (c + 2 < chunks) load_stage((c + 2) % 3, c + 2);

        const uint32_t sb = sbase + (uint32_t)(c % 3) * STAGE_B;
#pragma unroll
        for (int ks = 0; ks < 4; ks++) {
            uint32_t ah[2][4], al[2][4];
            uint32_t bh[NT][2], bl[NT][2];
#pragma unroll
            for (int mi = 0; mi < 2; mi++) {
                ldsm4(ah[mi], sb + rowA[mi] + colp[ks]);
                ldsm4(al[mi], sb + TILE_B + rowA[mi] + colp[ks]);
            }
#pragma unroll
            for (int nj = 0; nj < NR; nj++) {
                uint32_t t4[4];
                ldsm4(t4, sb + 2 * TILE_B + rowB[nj] + colp[ks]);
                bh[2 * nj][0] = t4[0]; bh[2 * nj][1] = t4[2];
                bh[2 * nj + 1][0] = t4[1]; bh[2 * nj + 1][1] = t4[3];
                ldsm4(t4, sb + 2 * TILE_B + BT_B + rowB[nj] + colp[ks]);
                bl[2 * nj][0] = t4[0]; bl[2 * nj][1] = t4[2];
                bl[2 * nj + 1][0] = t4[1]; bl[2 * nj + 1][1] = t4[3];
            }
#pragma unroll
            for (int mi = 0; mi < 2; mi++)
#pragma unroll
                for (int nt = 0; nt < NT; nt++) {
                    mma16816(acc[mi][nt], ah[mi], bh[nt][0], bh[nt][1]);
                    mma16816(acc[mi][nt], ah[mi], bl[nt][0], bl[nt][1]);
                    mma16816(acc[mi][nt], al[mi], bh[nt][0], bh[nt][1]);
                }
        }
    }

    __syncthreads();
    constexpr int SCS = NBLK + 4;
    float* sC = (float*)dsm;
#pragma unroll
    for (int mi = 0; mi < 2; mi++)
#pragma unroll
        for (int nt = 0; nt < NT; nt++) {
            int r0 = m_off + mi * 16 + (lane >> 2);
            int c0 = n_off + nt * 8 + (lane & 3) * 2;
            *(float2*)&sC[r0 * SCS + c0] = make_float2(acc[mi][nt][0], acc[mi][nt][1]);
            *(float2*)&sC[(r0 + 8) * SCS + c0] = make_float2(acc[mi][nt][2], acc[mi][nt][3]);
        }
    __syncthreads();
#pragma unroll
    for (int i = 0; i < (128 * NBLK) / GTHREADS; i++) {
        int idx = tid + i * GTHREADS;
        int r = idx / NBLK, cc = idx % NBLK;
        int gm = m0 + r, gn = n0 + cc;
        if (gm < NNODES && gn < Nout) {
            float v = fmaxf(sC[r * SCS + cc] + bias[gn], 0.f);
            if (outF) outF[(size_t)gm * Nout + gn] = v;
            if (outHi) {
                __nv_bfloat16 hi = __float2bfloat16(v);
                size_t o = (size_t)gm * strideO + colOff + gn;
                outHi[o] = hi;
                outLo[o] = __float2bfloat16(v - __bfloat162float(hi));
            }
        }
    }
}

// ---------------- final head: logits + log_softmax ----------------
__global__ void logits_kernel(const float* __restrict__ emb,
                              const float* __restrict__ lin2_w,
                              const float* __restrict__ lin2_b,
                              float* __restrict__ out)
{
    int gtid = blockIdx.x * blockDim.x + threadIdx.x;
    int node = gtid >> 5;
    int lane = gtid & 31;
    if (node >= NNODES) return;
    const float* e = emb + (size_t)node * DIM3;
    float s0 = 0.f, s1 = 0.f;
    for (int k = lane; k < DIM3; k += 32) {
        float v = e[k];
        s0 = fmaf(v, lin2_w[2 * k + 0], s0);
        s1 = fmaf(v, lin2_w[2 * k + 1], s1);
    }
#pragma unroll
    for (int o = 16; o; o >>= 1) {
        s0 += __shfl_down_sync(0xffffffffu, s0, o);
        s1 += __shfl_down_sync(0xffffffffu, s1, o);
    }
    if (lane == 0) {
        s0 += lin2_b[0];
        s1 += lin2_b[1];
        float m = fmaxf(s0, s1);
        float l = m + logf(expf(s0 - m) + expf(s1 - m));
        out[2 * node + 0] = s0 - l;
        out[2 * node + 1] = s1 - l;
    }
}

// ---------------- launch ----------------
extern "C" void kernel_launch(void* const* d_in, const int* in_sizes, int n_in,
                              void* d_out, int out_size)
{
    const float* x       = (const float*)d_in[0];
    const float* gene    = (const float*)d_in[1];
    const float* w_rel1  = (const float*)d_in[2];
    const float* root1   = (const float*)d_in[3];
    const float* b1      = (const float*)d_in[4];
    const float* w_rel2  = (const float*)d_in[5];
    const float* root2   = (const float*)d_in[6];
    const float* b2      = (const float*)d_in[7];
    const float* lin1_w  = (const float*)d_in[8];
    const float* lin1_b  = (const float*)d_in[9];
    const float* lin2_w  = (const float*)d_in[10];
    const float* lin2_b  = (const float*)d_in[11];
    const int*   ei = (const int*)d_in[12];
    const int*   et = (const int*)d_in[13];
    float* out = (float*)d_out;

    __nv_bfloat16 *Xch, *Xcl, *W1h, *W1l, *A1ch, *A1cl, *W2h, *W2l, *A2h, *A2l, *W3h, *W3l;
    float *A1;
    cudaGetSymbolAddress((void**)&Xch, g_Xcat_hi);  cudaGetSymbolAddress((void**)&Xcl, g_Xcat_lo);
    cudaGetSymbolAddress((void**)&W1h, g_W1hi);     cudaGetSymbolAddress((void**)&W1l, g_W1lo);
    cudaGetSymbolAddress((void**)&A1, g_A1);
    cudaGetSymbolAddress((void**)&A1ch, g_A1cat_hi); cudaGetSymbolAddress((void**)&A1cl, g_A1cat_lo);
    cudaGetSymbolAddress((void**)&W2h, g_W2hi);     cudaGetSymbolAddress((void**)&W2l, g_W2lo);
    cudaGetSymbolAddress((void**)&A2h, g_A2hi);     cudaGetSymbolAddress((void**)&A2l, g_A2lo);
    cudaGetSymbolAddress((void**)&W3h, g_W3hi);     cudaGetSymbolAddress((void**)&W3l, g_W3lo);

    const int SMEM128 = 3 * (2 * TILE_B + 2 * 128 * 128);   // 192 KB
    const int SMEM64  = 3 * (2 * TILE_B + 2 * 64 * 128);    // 144 KB
    cudaFuncSetAttribute(gemm_mma_kernel<128>, cudaFuncAttributeMaxDynamicSharedMemorySize, SMEM128);
    cudaFuncSetAttribute(gemm_mma_kernel<64>,  cudaFuncAttributeMaxDynamicSharedMemorySize, SMEM64);

    // 1-4) edge preprocessing (4 launches)
    zero_cnt_kernel<<<(NSEG + 255) / 256, 256>>>();
    count_kernel<<<(N_EDGES + 255) / 256, 256>>>(ei, et);
    scan_kernel<<<1, 1024>>>();
    fill_kernel<<<(N_EDGES + 255) / 256, 256>>>(ei, et);

    // 5) fused prep: xfill + W1/W2/W3 transpose-splits + layer-1 aggregation
    fused_prep_kernel<<<GFUSED, 256>>>(x, gene, w_rel1, root1, w_rel2, root2, lin1_w);

    // 6) layer-1 GEMM  <-- 6th launch: captured by ncu (-s 5 -c 1)
    gemm_mma_kernel<128><<<dim3(NP1 / 128, MPAD / 128), GTHREADS, SMEM128>>>(
        Xch, Xcl, W1h, W1l, KC1, DIM1, b1, A1, A1ch, A1cl, KC2, 4 * KP2);

    // 7) layer-2 input assembly
    agg_seg_kernel<6><<<NSEG, 256>>>(A1, A1, NNODES, DIM1, KP2, KC2, A1ch, A1cl);

    // 8) layer-2 GEMM
    gemm_mma_kernel<64><<<dim3(NP2 / 64, MPAD / 128), GTHREADS, SMEM64>>>(
        A1ch, A1cl, W2h, W2l, KC2, DIM2, b2, nullptr, A2h, A2l, KP3, 0);

    // 9) lin1 -> emb in output buffer
    float* emb = out + 2 * NNODES;
    gemm_mma_kernel<128><<<dim3(NP3 / 128, MPAD / 128), GTHREADS, SMEM128>>>(
        A2h, A2l, W3h, W3l, KP3, DIM3, lin1_b, emb, nullptr, nullptr, 0, 0);

    // 10) lin2 + log_softmax
    logits_kernel<<<(NNODES * 32 + 255) / 256, 256>>>(emb, lin2_w, lin2_b, out);
}

// round 14
// speedup vs baseline: 2.0337x; 2.0337x over previous
#include <cuda_runtime.h>
#include <cuda_fp16.h>
#include <cstdint>
#include <math.h>

// ---------------- problem constants ----------------
#define N_DRUGS   4000
#define N_GENES   4264
#define NNODES    8264
#define IN_DIM    1613
#define DIM1      1340
#define DIM2      920
#define DIM3      740
#define N_REL     4
#define N_EDGES   100000
#define NSEG      (NNODES * N_REL)     // 33056

#define MPAD      8320                 // 65 * 128
#define KP1       1664                 // pad(1613, 64)
#define KP2       1344                 // pad(1340, 64)
#define KP3       960                  // pad(920, 64)
#define KC1       (5 * KP1)            // 8320
#define KC2       (5 * KP2)            // 6720
#define NP1       1408                 // 11 * 128
#define NP2       1024                 // 8 * 128
#define NP3       768                  // 6 * 128

// ---------------- device scratch ----------------
__device__ __half g_Xcat_hi[(size_t)MPAD * KC1];
__device__ __half g_Xcat_lo[(size_t)MPAD * KC1];
__device__ __half g_W1h[(size_t)NP1 * KC1];
__device__ float  g_A1[(size_t)NNODES * DIM1];
__device__ __half g_A1cat_hi[(size_t)MPAD * KC2];
__device__ __half g_A1cat_lo[(size_t)MPAD * KC2];
__device__ __half g_W2h[(size_t)NP2 * KC2];
__device__ __half g_A2hi[(size_t)MPAD * KP3];
__device__ __half g_A2lo[(size_t)MPAD * KP3];
__device__ __half g_W3h[(size_t)NP3 * KP3];
__device__ int g_cnt[NSEG];
__device__ int g_seg_start[NSEG + 1];
__device__ int g_cursor[NSEG];
__device__ int g_esrc[N_EDGES];

// ---------------- PTX helpers (plain sm_80+ instructions only) ----------------
__device__ __forceinline__ uint32_t smem_to_u32(const void* p) {
    uint32_t a;
    asm("{ .reg .u64 t; cvta.to.shared.u64 t, %1; cvt.u32.u64 %0, t; }" : "=r"(a) : "l"(p));
    return a;
}
#define CP_ASYNC16(dst, src) \
    asm volatile("cp.async.cg.shared.global [%0], [%1], 16;" :: "r"(dst), "l"(src) : "memory")
#define CP_ASYNC_COMMIT() asm volatile("cp.async.commit_group;" ::: "memory")
#define CP_ASYNC_WAIT(n)  asm volatile("cp.async.wait_group %0;" :: "n"(n) : "memory")

__device__ __forceinline__ void ldsm4(uint32_t (&r)[4], uint32_t addr) {
    asm volatile("ldmatrix.sync.aligned.m8n8.x4.shared.b16 {%0,%1,%2,%3}, [%4];"
                 : "=r"(r[0]), "=r"(r[1]), "=r"(r[2]), "=r"(r[3]) : "r"(addr));
}
__device__ __forceinline__ void mma16816h(float (&d)[4], const uint32_t (&a)[4],
                                          uint32_t b0, uint32_t b1) {
    asm volatile(
        "mma.sync.aligned.m16n8k16.row.col.f32.f16.f16.f32 "
        "{%0,%1,%2,%3}, {%4,%5,%6,%7}, {%8,%9}, {%0,%1,%2,%3};"
        : "+f"(d[0]), "+f"(d[1]), "+f"(d[2]), "+f"(d[3])
        : "r"(a[0]), "r"(a[1]), "r"(a[2]), "r"(a[3]), "r"(b0), "r"(b1));
}
#define SWZ(off) ((off) ^ (((off) >> 3) & 0x70))

__device__ __forceinline__ void split_h(float v, __half& hi, __half& lo) {
    __half h = __float2half(v);
    hi = h;
    lo = __float2half(v - __half2float(h));
}

// ---------------- prep: x -> Xcat root slot (fp16 hi/lo) ----------------
__global__ void xfill_kernel(const float* __restrict__ x, const float* __restrict__ gene)
{
    size_t i = (size_t)blockIdx.x * blockDim.x + threadIdx.x;
    const size_t TOT = (size_t)NNODES * IN_DIM;
    if (i >= TOT) return;
    int node = (int)(i / IN_DIM);
    int k = (int)(i % IN_DIM);
    float v = (node < N_DRUGS) ? x[(size_t)node * IN_DIM + k]
                               : gene[(size_t)(node - N_DRUGS) * IN_DIM + k];
    size_t o = (size_t)node * KC1 + 4 * KP1 + k;
    split_h(v, g_Xcat_hi[o], g_Xcat_lo[o]);
}

// transpose W[K][N] (z slabs) -> Wcat[n][z*Kpad + k] single fp16, zero-padded
__global__ void transpose_half_kernel(const float* __restrict__ Wrel,
                                      const float* __restrict__ Wroot,
                                      __half* __restrict__ Th,
                                      int K, int N, int Kpad, int KC)
{
    __shared__ float t[32][33];
    int z = blockIdx.z;
    const float* W = (Wrel != nullptr && z < N_REL) ? (Wrel + (size_t)z * K * N) : Wroot;
    int k0 = blockIdx.x * 32;
    int n0 = blockIdx.y * 32;
    int tx = threadIdx.x, ty = threadIdx.y;
#pragma unroll
    for (int i = 0; i < 4; i++) {
        int k = k0 + ty + i * 8;
        int n = n0 + tx;
        t[ty + i * 8][tx] = (k < K && n < N) ? W[(size_t)k * N + n] : 0.f;
    }
    __syncthreads();
#pragma unroll
    for (int i = 0; i < 4; i++) {
        int n = n0 + ty + i * 8;
        int kk = k0 + tx;
        size_t o = (size_t)n * KC + (size_t)z * Kpad + kk;
        Th[o] = __float2half(t[tx][ty + i * 8]);
    }
}

// ---------------- edge preprocessing ----------------
__global__ void zero_cnt_kernel()
{
    int i = blockIdx.x * blockDim.x + threadIdx.x;
    if (i < NSEG) g_cnt[i] = 0;
}
__global__ void count_kernel(const int* __restrict__ ei, const int* __restrict__ et)
{
    int e = blockIdx.x * blockDim.x + threadIdx.x;
    if (e >= N_EDGES) return;
    atomicAdd(&g_cnt[ei[N_EDGES + e] * N_REL + et[e]], 1);
}
__global__ void scan_kernel()
{
    __shared__ int part[1024];
    const int CHK = (NSEG + 1023) / 1024;
    int tid = threadIdx.x;
    int degs[CHK];
    int mysum = 0;
#pragma unroll
    for (int i = 0; i < CHK; i++) {
        int d = tid * CHK + i;
        int dg = (d < NSEG) ? g_cnt[d] : 0;
        degs[i] = dg;
        mysum += dg;
    }
    part[tid] = mysum;
    __syncthreads();
    if (tid == 0) {
        int run = 0;
        for (int t = 0; t < 1024; t++) { int v = part[t]; part[t] = run; run += v; }
        g_seg_start[NSEG] = run;
    }
    __syncthreads();
    int off = part[tid];
#pragma unroll
    for (int i = 0; i < CHK; i++) {
        int d = tid * CHK + i;
        if (d < NSEG) { g_seg_start[d] = off; g_cursor[d] = off; off += degs[i]; }
    }
}
__global__ void fill_kernel(const int* __restrict__ ei, const int* __restrict__ et)
{
    int e = blockIdx.x * blockDim.x + threadIdx.x;
    if (e >= N_EDGES) return;
    int seg = ei[N_EDGES + e] * N_REL + et[e];
    g_esrc[atomicAdd(&g_cursor[seg], 1)] = ei[e];
}

// ---------------- segment-mean aggregation, emits fp16 hi/lo ----------------
template <int CH>
__global__ void agg_seg_kernel(const float* __restrict__ src0, const float* __restrict__ src1,
                               int splitRow, int D, int Kpad, int KC,
                               __half* __restrict__ outHi, __half* __restrict__ outLo)
{
    int seg = blockIdx.x;
    int s = g_seg_start[seg];
    int e = g_seg_start[seg + 1];
    if (s == e) return;
    int tid = threadIdx.x;
    float acc[CH];
#pragma unroll
    for (int j = 0; j < CH; j++) acc[j] = 0.f;
    for (int p = s; p < e; p++) {
        int sn = g_esrc[p];
        const float* row = (sn < splitRow) ? (src0 + (size_t)sn * D)
                                           : (src1 + (size_t)(sn - splitRow) * D);
#pragma unroll
        for (int j = 0; j < CH; j++) {
            int o = tid + j * 256;
            if (o < D) acc[j] += row[o];
        }
    }
    float inv = 1.0f / (float)(e - s);
    int node = seg >> 2, rel = seg & 3;
    size_t base = (size_t)node * KC + (size_t)rel * Kpad;
#pragma unroll
    for (int j = 0; j < CH; j++) {
        int o = tid + j * 256;
        if (o < D) split_h(acc[j] * inv, outHi[base + o], outLo[base + o]);
    }
}

// ---------------- mma.sync fp16 2-term GEMM ----------------
// C[m][n] = relu( sum_k A[m][k]*W[n][k] + bias[n] ),  A = Ahi+Alo (fp16), W = fp16
// CTA tile 128 x NBLK, BK=64, 3-stage cp.async, 16 warps (4m x 4n).
#define TILE_B  (128 * 128)          // A tile bytes (128 rows x 128B)
#define GTHREADS 512

template <int NBLK>
__global__ void __launch_bounds__(GTHREADS, 1)
gemm_fp16_kernel(const __half* __restrict__ Ahi, const __half* __restrict__ Alo,
                 const __half* __restrict__ B,
                 int KC, int Nout, const float* __restrict__ bias,
                 float* __restrict__ outF,
                 __half* __restrict__ outHi, __half* __restrict__ outLo,
                 int strideO, int colOff)
{
    constexpr int BT_B = NBLK * 128;                 // B tile bytes
    constexpr int STAGE_B = 2 * TILE_B + BT_B;       // 48 KB @ NBLK=128
    constexpr int WN = NBLK / 4;
    constexpr int NR = WN / 16;
    constexpr int NT = WN / 8;
    constexpr int LOADS = (2048 + 8 * NBLK) / GTHREADS;

    extern __shared__ char dsm[];
    const uint32_t sbase = smem_to_u32(dsm);
    const int tid = threadIdx.x;
    const int lane = tid & 31;
    const int wid = tid >> 5;
    const int m_off = (wid >> 2) * 32;
    const int n_off = (wid & 3) * WN;
    const int m0 = blockIdx.y * 128;
    const int n0 = blockIdx.x * NBLK;

    const int arow = lane & 15;
    const uint32_t xorv = (uint32_t)(arow & 7) << 4;
    uint32_t colp[4];
#pragma unroll
    for (int ks = 0; ks < 4; ks++)
        colp[ks] = ((uint32_t)(ks * 32 + ((lane >> 4) * 16))) ^ xorv;
    uint32_t rowA[2], rowB[NR];
#pragma unroll
    for (int mi = 0; mi < 2; mi++) rowA[mi] = (uint32_t)(m_off + mi * 16 + arow) * 128u;
#pragma unroll
    for (int nj = 0; nj < NR; nj++) rowB[nj] = (uint32_t)(n_off + nj * 16 + arow) * 128u;

    float acc[2][NT][4];
#pragma unroll
    for (int mi = 0; mi < 2; mi++)
#pragma unroll
        for (int nt = 0; nt < NT; nt++)
#pragma unroll
            for (int q = 0; q < 4; q++) acc[mi][nt][q] = 0.f;

    const int chunks = KC >> 6;

    auto load_stage = [&](int slot, int c) {
        const int k0 = c << 6;
        const uint32_t base = sbase + (uint32_t)slot * STAGE_B;
#pragma unroll
        for (int i = 0; i < LOADS; i++) {
            int idx = tid + i * GTHREADS;
            const __half* g;
            uint32_t d;
            if (idx < 2048) {
                int t = idx >> 10;              // 0: Ahi, 1: Alo
                int r = (idx >> 3) & 127, j = idx & 7;
                g = (t ? Alo : Ahi) + (size_t)(m0 + r) * KC + k0 + j * 8;
                d = base + (uint32_t)t * TILE_B + SWZ((uint32_t)(r * 128 + j * 16));
            } else {
                int i2 = idx - 2048;            // B: 8*NBLK chunks of 16B
                int r = i2 >> 3, j = i2 & 7;
                g = B + (size_t)(n0 + r) * KC + k0 + j * 8;
                d = base + 2 * TILE_B + SWZ((uint32_t)(r * 128 + j * 16));
            }
            CP_ASYNC16(d, (const void*)g);
        }
        CP_ASYNC_COMMIT();
    };

    load_stage(0, 0);
    if (chunks > 1) load_stage(1, 1);

    for (int c = 0; c < chunks; c++) {
        if (c + 1 < chunks) CP_ASYNC_WAIT(1);
        else                CP_ASYNC_WAIT(0);
        __syncthreads();
        if (c + 2 < chunks) load_stage((c + 2) % 3, c + 2);

        const uint32_t sb = sbase + (uint32_t)(c % 3) * STAGE_B;
#pragma unroll
        for (int ks = 0; ks < 4; ks++) {
            uint32_t ah[2][4], al[2][4];
            uint32_t bf[NT][2];
#pragma unroll
            for (int mi = 0; mi < 2; mi++) {
                ldsm4(ah[mi], sb + rowA[mi] + colp[ks]);
                ldsm4(al[mi], sb + TILE_B + rowA[mi] + colp[ks]);
            }
#pragma unroll
            for (int nj = 0; nj < NR; nj++) {
                uint32_t t4[4];
                ldsm4(t4, sb + 2 * TILE_B + rowB[nj] + colp[ks]);
                bf[2 * nj][0] = t4[0]; bf[2 * nj][1] = t4[2];
                bf[2 * nj + 1][0] = t4[1]; bf[2 * nj + 1][1] = t4[3];
            }
#pragma unroll
            for (int mi = 0; mi < 2; mi++)
#pragma unroll
                for (int nt = 0; nt < NT; nt++) {
                    mma16816h(acc[mi][nt], ah[mi], bf[nt][0], bf[nt][1]);
                    mma16816h(acc[mi][nt], al[mi], bf[nt][0], bf[nt][1]);
                }
        }
    }

    // ---- epilogue: regs -> smem -> gmem (bias + relu; fp32 and/or fp16 hi/lo) ----
    __syncthreads();
    constexpr int SCS = NBLK + 4;
    float* sC = (float*)dsm;
#pragma unroll
    for (int mi = 0; mi < 2; mi++)
#pragma unroll
        for (int nt = 0; nt < NT; nt++) {
            int r0 = m_off + mi * 16 + (lane >> 2);
            int c0 = n_off + nt * 8 + (lane & 3) * 2;
            *(float2*)&sC[r0 * SCS + c0] = make_float2(acc[mi][nt][0], acc[mi][nt][1]);
            *(float2*)&sC[(r0 + 8) * SCS + c0] = make_float2(acc[mi][nt][2], acc[mi][nt][3]);
        }
    __syncthreads();
#pragma unroll
    for (int i = 0; i < (128 * NBLK) / GTHREADS; i++) {
        int idx = tid + i * GTHREADS;
        int r = idx / NBLK, cc = idx % NBLK;
        int gm = m0 + r, gn = n0 + cc;
        if (gm < NNODES && gn < Nout) {
            float v = fmaxf(sC[r * SCS + cc] + bias[gn], 0.f);
            if (outF) outF[(size_t)gm * Nout + gn] = v;
            if (outHi) {
                size_t o = (size_t)gm * strideO + colOff + gn;
                split_h(v, outHi[o], outLo[o]);
            }
        }
    }
}

// ---------------- final head: logits + log_softmax ----------------
__global__ void logits_kernel(const float* __restrict__ emb,
                              const float* __restrict__ lin2_w,
                              const float* __restrict__ lin2_b,
                              float* __restrict__ out)
{
    int gtid = blockIdx.x * blockDim.x + threadIdx.x;
    int node = gtid >> 5;
    int lane = gtid & 31;
    if (node >= NNODES) return;
    const float* e = emb + (size_t)node * DIM3;
    float s0 = 0.f, s1 = 0.f;
    for (int k = lane; k < DIM3; k += 32) {
        float v = e[k];
        s0 = fmaf(v, lin2_w[2 * k + 0], s0);
        s1 = fmaf(v, lin2_w[2 * k + 1], s1);
    }
#pragma unroll
    for (int o = 16; o; o >>= 1) {
        s0 += __shfl_down_sync(0xffffffffu, s0, o);
        s1 += __shfl_down_sync(0xffffffffu, s1, o);
    }
    if (lane == 0) {
        s0 += lin2_b[0];
        s1 += lin2_b[1];
        float m = fmaxf(s0, s1);
        float l = m + logf(expf(s0 - m) + expf(s1 - m));
        out[2 * node + 0] = s0 - l;
        out[2 * node + 1] = s1 - l;
    }
}

// ---------------- launch ----------------
extern "C" void kernel_launch(void* const* d_in, const int* in_sizes, int n_in,
                              void* d_out, int out_size)
{
    const float* x       = (const float*)d_in[0];
    const float* gene    = (const float*)d_in[1];
    const float* w_rel1  = (const float*)d_in[2];
    const float* root1   = (const float*)d_in[3];
    const float* b1      = (const float*)d_in[4];
    const float* w_rel2  = (const float*)d_in[5];
    const float* root2   = (const float*)d_in[6];
    const float* b2      = (const float*)d_in[7];
    const float* lin1_w  = (const float*)d_in[8];
    const float* lin1_b  = (const float*)d_in[9];
    const float* lin2_w  = (const float*)d_in[10];
    const float* lin2_b  = (const float*)d_in[11];
    const int*   ei = (const int*)d_in[12];
    const int*   et = (const int*)d_in[13];
    float* out = (float*)d_out;

    __half *Xch, *Xcl, *W1h, *A1ch, *A1cl, *W2h, *A2h, *A2l, *W3h;
    float *A1;
    cudaGetSymbolAddress((void**)&Xch, g_Xcat_hi);  cudaGetSymbolAddress((void**)&Xcl, g_Xcat_lo);
    cudaGetSymbolAddress((void**)&W1h, g_W1h);
    cudaGetSymbolAddress((void**)&A1, g_A1);
    cudaGetSymbolAddress((void**)&A1ch, g_A1cat_hi); cudaGetSymbolAddress((void**)&A1cl, g_A1cat_lo);
    cudaGetSymbolAddress((void**)&W2h, g_W2h);
    cudaGetSymbolAddress((void**)&A2h, g_A2hi);     cudaGetSymbolAddress((void**)&A2l, g_A2lo);
    cudaGetSymbolAddress((void**)&W3h, g_W3h);

    const int SMEM128 = 3 * (2 * TILE_B + 128 * 128);   // 144 KB
    cudaFuncSetAttribute(gemm_fp16_kernel<128>, cudaFuncAttributeMaxDynamicSharedMemorySize, SMEM128);

    // 1) weight transposes (single fp16)
    {
        dim3 tb(32, 8);
        transpose_half_kernel<<<dim3(KP1 / 32, NP1 / 32, 5), tb>>>(w_rel1, root1, W1h, IN_DIM, DIM1, KP1, KC1);
        transpose_half_kernel<<<dim3(KP2 / 32, NP2 / 32, 5), tb>>>(w_rel2, root2, W2h, DIM1, DIM2, KP2, KC2);
        transpose_half_kernel<<<dim3(KP3 / 32, NP3 / 32, 1), tb>>>(nullptr, lin1_w, W3h, DIM2, DIM3, KP3, KP3);
    }
    // 2) edge preprocessing
    zero_cnt_kernel<<<(NSEG + 255) / 256, 256>>>();
    count_kernel<<<(N_EDGES + 255) / 256, 256>>>(ei, et);
    scan_kernel<<<1, 1024>>>();
    fill_kernel<<<(N_EDGES + 255) / 256, 256>>>(ei, et);

    // 3) layer-1 input assembly
    {
        size_t tot = (size_t)NNODES * IN_DIM;
        xfill_kernel<<<(unsigned)((tot + 255) / 256), 256>>>(x, gene);
    }
    agg_seg_kernel<7><<<NSEG, 256>>>(x, gene, N_DRUGS, IN_DIM, KP1, KC1, Xch, Xcl);

    // 4) layer-1 GEMM: A1 fp32 + fp16 hi/lo into A1cat root slot
    gemm_fp16_kernel<128><<<dim3(NP1 / 128, MPAD / 128), GTHREADS, SMEM128>>>(
        Xch, Xcl, W1h, KC1, DIM1, b1, A1, A1ch, A1cl, KC2, 4 * KP2);

    // 5) layer-2 input assembly
    agg_seg_kernel<6><<<NSEG, 256>>>(A1, A1, NNODES, DIM1, KP2, KC2, A1ch, A1cl);

    // 6) layer-2 GEMM
    gemm_fp16_kernel<128><<<dim3(NP2 / 128, MPAD / 128), GTHREADS, SMEM128>>>(
        A1ch, A1cl, W2h, KC2, DIM2, b2, nullptr, A2h, A2l, KP3, 0);

    // 7) lin1 -> emb in output buffer
    float* emb = out + 2 * NNODES;
    gemm_fp16_kernel<128><<<dim3(NP3 / 128, MPAD / 128), GTHREADS, SMEM128>>>(
        A2h, A2l, W3h, KP3, DIM3, lin1_b, emb, nullptr, nullptr, 0, 0);

    // 8) lin2 + log_softmax
    logits_kernel<<<(NNODES * 32 + 255) / 256, 256>>>(emb, lin2_w, lin2_b, out);
}

// round 15
// speedup vs baseline: 2.0541x; 1.0100x over previous
#include <cuda_runtime.h>
#include <cuda_fp16.h>
#include <cstdint>
#include <math.h>

// ---------------- problem constants ----------------
#define N_DRUGS   4000
#define N_GENES   4264
#define NNODES    8264
#define IN_DIM    1613
#define DIM1      1340
#define DIM2      920
#define DIM3      740
#define N_REL     4
#define N_EDGES   100000
#define NSEG      (NNODES * N_REL)     // 33056

#define MPAD      8320                 // 65 * 128
#define KP1       1664                 // pad(1613, 64)
#define KP2       1344                 // pad(1340, 64)
#define KP3       960                  // pad(920, 64)
#define KC1       (5 * KP1)            // 8320
#define KC2       (5 * KP2)            // 6720
#define NP1       1408                 // 11 * 128
#define NP2       1024                 // 8 * 128
#define NP3       768                  // 6 * 128

#define XH_STR    1616                 // fp16 x copy row stride (16B aligned, >= IN_DIM)
#define A1H_STR   1344                 // fp16 A1 copy row stride (16B aligned, >= DIM1)

// ---------------- device scratch ----------------
__device__ __half g_Xcat_hi[(size_t)MPAD * KC1];
__device__ __half g_Xcat_lo[(size_t)MPAD * KC1];
__device__ __half g_W1h[(size_t)NP1 * KC1];
__device__ __half g_Xh16[(size_t)NNODES * XH_STR];   // contiguous fp16 x (gather source)
__device__ __half g_A1h16[(size_t)NNODES * A1H_STR]; // contiguous fp16 A1 (gather source)
__device__ __half g_A1cat_hi[(size_t)MPAD * KC2];
__device__ __half g_A1cat_lo[(size_t)MPAD * KC2];
__device__ __half g_W2h[(size_t)NP2 * KC2];
__device__ __half g_A2hi[(size_t)MPAD * KP3];
__device__ __half g_A2lo[(size_t)MPAD * KP3];
__device__ __half g_W3h[(size_t)NP3 * KP3];
__device__ int g_cnt[NSEG];
__device__ int g_seg_start[NSEG + 1];
__device__ int g_cursor[NSEG];
__device__ int g_esrc[N_EDGES];

// ---------------- PTX helpers (plain sm_80+ instructions only) ----------------
__device__ __forceinline__ uint32_t smem_to_u32(const void* p) {
    uint32_t a;
    asm("{ .reg .u64 t; cvta.to.shared.u64 t, %1; cvt.u32.u64 %0, t; }" : "=r"(a) : "l"(p));
    return a;
}
#define CP_ASYNC16(dst, src) \
    asm volatile("cp.async.cg.shared.global [%0], [%1], 16;" :: "r"(dst), "l"(src) : "memory")
#define CP_ASYNC_COMMIT() asm volatile("cp.async.commit_group;" ::: "memory")
#define CP_ASYNC_WAIT(n)  asm volatile("cp.async.wait_group %0;" :: "n"(n) : "memory")

__device__ __forceinline__ void ldsm4(uint32_t (&r)[4], uint32_t addr) {
    asm volatile("ldmatrix.sync.aligned.m8n8.x4.shared.b16 {%0,%1,%2,%3}, [%4];"
                 : "=r"(r[0]), "=r"(r[1]), "=r"(r[2]), "=r"(r[3]) : "r"(addr));
}
__device__ __forceinline__ void mma16816h(float (&d)[4], const uint32_t (&a)[4],
                                          uint32_t b0, uint32_t b1) {
    asm volatile(
        "mma.sync.aligned.m16n8k16.row.col.f32.f16.f16.f32 "
        "{%0,%1,%2,%3}, {%4,%5,%6,%7}, {%8,%9}, {%0,%1,%2,%3};"
        : "+f"(d[0]), "+f"(d[1]), "+f"(d[2]), "+f"(d[3])
        : "r"(a[0]), "r"(a[1]), "r"(a[2]), "r"(a[3]), "r"(b0), "r"(b1));
}
#define SWZ(off) ((off) ^ (((off) >> 3) & 0x70))

__device__ __forceinline__ void split_h(float v, __half& hi, __half& lo) {
    __half h = __float2half(v);
    hi = h;
    lo = __float2half(v - __half2float(h));
}

// ---------------- prep: x -> Xcat root slot (fp16 hi/lo) + contiguous fp16 copy ----------------
__global__ void xfill_kernel(const float* __restrict__ x, const float* __restrict__ gene)
{
    size_t i = (size_t)blockIdx.x * blockDim.x + threadIdx.x;
    const size_t TOT = (size_t)NNODES * IN_DIM;
    if (i >= TOT) return;
    int node = (int)(i / IN_DIM);
    int k = (int)(i % IN_DIM);
    float v = (node < N_DRUGS) ? x[(size_t)node * IN_DIM + k]
                               : gene[(size_t)(node - N_DRUGS) * IN_DIM + k];
    size_t o = (size_t)node * KC1 + 4 * KP1 + k;
    __half hi, lo;
    split_h(v, hi, lo);
    g_Xcat_hi[o] = hi;
    g_Xcat_lo[o] = lo;
    g_Xh16[(size_t)node * XH_STR + k] = hi;
}

// transpose W[K][N] (z slabs) -> Wcat[n][z*Kpad + k] single fp16, zero-padded
__global__ void transpose_half_kernel(const float* __restrict__ Wrel,
                                      const float* __restrict__ Wroot,
                                      __half* __restrict__ Th,
                                      int K, int N, int Kpad, int KC)
{
    __shared__ float t[32][33];
    int z = blockIdx.z;
    const float* W = (Wrel != nullptr && z < N_REL) ? (Wrel + (size_t)z * K * N) : Wroot;
    int k0 = blockIdx.x * 32;
    int n0 = blockIdx.y * 32;
    int tx = threadIdx.x, ty = threadIdx.y;
#pragma unroll
    for (int i = 0; i < 4; i++) {
        int k = k0 + ty + i * 8;
        int n = n0 + tx;
        t[ty + i * 8][tx] = (k < K && n < N) ? W[(size_t)k * N + n] : 0.f;
    }
    __syncthreads();
#pragma unroll
    for (int i = 0; i < 4; i++) {
        int n = n0 + ty + i * 8;
        int kk = k0 + tx;
        size_t o = (size_t)n * KC + (size_t)z * Kpad + kk;
        Th[o] = __float2half(t[tx][ty + i * 8]);
    }
}

// ---------------- edge preprocessing ----------------
__global__ void zero_cnt_kernel()
{
    int i = blockIdx.x * blockDim.x + threadIdx.x;
    if (i < NSEG) g_cnt[i] = 0;
}
__global__ void count_kernel(const int* __restrict__ ei, const int* __restrict__ et)
{
    int e = blockIdx.x * blockDim.x + threadIdx.x;
    if (e >= N_EDGES) return;
    atomicAdd(&g_cnt[ei[N_EDGES + e] * N_REL + et[e]], 1);
}
__global__ void scan_kernel()
{
    __shared__ int part[1024];
    const int CHK = (NSEG + 1023) / 1024;
    int tid = threadIdx.x;
    int degs[CHK];
    int mysum = 0;
#pragma unroll
    for (int i = 0; i < CHK; i++) {
        int d = tid * CHK + i;
        int dg = (d < NSEG) ? g_cnt[d] : 0;
        degs[i] = dg;
        mysum += dg;
    }
    part[tid] = mysum;
    __syncthreads();
    if (tid == 0) {
        int run = 0;
        for (int t = 0; t < 1024; t++) { int v = part[t]; part[t] = run; run += v; }
        g_seg_start[NSEG] = run;
    }
    __syncthreads();
    int off = part[tid];
#pragma unroll
    for (int i = 0; i < CHK; i++) {
        int d = tid * CHK + i;
        if (d < NSEG) { g_seg_start[d] = off; g_cursor[d] = off; off += degs[i]; }
    }
}
__global__ void fill_kernel(const int* __restrict__ ei, const int* __restrict__ et)
{
    int e = blockIdx.x * blockDim.x + threadIdx.x;
    if (e >= N_EDGES) return;
    int seg = ei[N_EDGES + e] * N_REL + et[e];
    g_esrc[atomicAdd(&g_cursor[seg], 1)] = ei[e];
}

// ---------------- segment-mean aggregation from fp16 source (half2 vectorized) ----------------
// D2 = half2 units per row; src rows zero-padded to even/stride. Emits fp16 hi/lo cat slots.
template <int CH2>
__global__ void agg_seg_h_kernel(const __half* __restrict__ src, int strideH,
                                 int D2, int Kpad, int KC,
                                 __half* __restrict__ outHi, __half* __restrict__ outLo)
{
    int seg = blockIdx.x;
    int s = g_seg_start[seg];
    int e = g_seg_start[seg + 1];
    if (s == e) return;
    int tid = threadIdx.x;
    float2 acc[CH2];
#pragma unroll
    for (int j = 0; j < CH2; j++) acc[j] = make_float2(0.f, 0.f);
    for (int p = s; p < e; p++) {
        int sn = g_esrc[p];
        const __half2* row = (const __half2*)(src + (size_t)sn * strideH);
#pragma unroll
        for (int j = 0; j < CH2; j++) {
            int o2 = tid + j * 256;
            if (o2 < D2) {
                float2 v = __half22float2(row[o2]);
                acc[j].x += v.x;
                acc[j].y += v.y;
            }
        }
    }
    float inv = 1.0f / (float)(e - s);
    int node = seg >> 2, rel = seg & 3;
    size_t base2 = ((size_t)node * KC + (size_t)rel * Kpad) >> 1;   // half2 index
    __half2* hi2 = (__half2*)outHi;
    __half2* lo2 = (__half2*)outLo;
#pragma unroll
    for (int j = 0; j < CH2; j++) {
        int o2 = tid + j * 256;
        if (o2 < D2) {
            float vx = acc[j].x * inv, vy = acc[j].y * inv;
            __half hx, lx, hy, ly;
            split_h(vx, hx, lx);
            split_h(vy, hy, ly);
            hi2[base2 + o2] = __halves2half2(hx, hy);
            lo2[base2 + o2] = __halves2half2(lx, ly);
        }
    }
}

// ---------------- mma.sync fp16 2-term GEMM ----------------
// C[m][n] = relu( sum_k A[m][k]*W[n][k] + bias[n] ),  A = Ahi+Alo (fp16), W = fp16
// CTA tile 128 x NBLK, BK=64, 3-stage cp.async, 16 warps (4m x 4n).
#define TILE_B  (128 * 128)          // A tile bytes (128 rows x 128B)
#define GTHREADS 512

template <int NBLK>
__global__ void __launch_bounds__(GTHREADS, 1)
gemm_fp16_kernel(const __half* __restrict__ Ahi, const __half* __restrict__ Alo,
                 const __half* __restrict__ B,
                 int KC, int Nout, const float* __restrict__ bias,
                 float* __restrict__ outF,
                 __half* __restrict__ outH16, int strideH16,
                 __half* __restrict__ outHi, __half* __restrict__ outLo,
                 int strideO, int colOff)
{
    constexpr int BT_B = NBLK * 128;                 // B tile bytes
    constexpr int STAGE_B = 2 * TILE_B + BT_B;       // 48 KB @ NBLK=128
    constexpr int WN = NBLK / 4;
    constexpr int NR = WN / 16;
    constexpr int NT = WN / 8;
    constexpr int LOADS = (2048 + 8 * NBLK) / GTHREADS;

    extern __shared__ char dsm[];
    const uint32_t sbase = smem_to_u32(dsm);
    const int tid = threadIdx.x;
    const int lane = tid & 31;
    const int wid = tid >> 5;
    const int m_off = (wid >> 2) * 32;
    const int n_off = (wid & 3) * WN;
    const int m0 = blockIdx.y * 128;
    const int n0 = blockIdx.x * NBLK;

    const int arow = lane & 15;
    const uint32_t xorv = (uint32_t)(arow & 7) << 4;
    uint32_t colp[4];
#pragma unroll
    for (int ks = 0; ks < 4; ks++)
        colp[ks] = ((uint32_t)(ks * 32 + ((lane >> 4) * 16))) ^ xorv;
    uint32_t rowA[2], rowB[NR];
#pragma unroll
    for (int mi = 0; mi < 2; mi++) rowA[mi] = (uint32_t)(m_off + mi * 16 + arow) * 128u;
#pragma unroll
    for (int nj = 0; nj < NR; nj++) rowB[nj] = (uint32_t)(n_off + nj * 16 + arow) * 128u;

    float acc[2][NT][4];
#pragma unroll
    for (int mi = 0; mi < 2; mi++)
#pragma unroll
        for (int nt = 0; nt < NT; nt++)
#pragma unroll
            for (int q = 0; q < 4; q++) acc[mi][nt][q] = 0.f;

    const int chunks = KC >> 6;

    auto load_stage = [&](int slot, int c) {
        const int k0 = c << 6;
        const uint32_t base = sbase + (uint32_t)slot * STAGE_B;
#pragma unroll
        for (int i = 0; i < LOADS; i++) {
            int idx = tid + i * GTHREADS;
            const __half* g;
            uint32_t d;
            if (idx < 2048) {
                int t = idx >> 10;              // 0: Ahi, 1: Alo
                int r = (idx >> 3) & 127, j = idx & 7;
                g = (t ? Alo : Ahi) + (size_t)(m0 + r) * KC + k0 + j * 8;
                d = base + (uint32_t)t * TILE_B + SWZ((uint32_t)(r * 128 + j * 16));
            } else {
                int i2 = idx - 2048;            // B: 8*NBLK chunks of 16B
                int r = i2 >> 3, j = i2 & 7;
                g = B + (size_t)(n0 + r) * KC + k0 + j * 8;
                d = base + 2 * TILE_B + SWZ((uint32_t)(r * 128 + j * 16));
            }
            CP_ASYNC16(d, (const void*)g);
        }
        CP_ASYNC_COMMIT();
    };

    load_stage(0, 0);
    if (chunks > 1) load_stage(1, 1);

    for (int c = 0; c < chunks; c++) {
        if (c + 1 < chunks) CP_ASYNC_WAIT(1);
        else                CP_ASYNC_WAIT(0);
        __syncthreads();
        if (c + 2 < chunks) load_stage((c + 2) % 3, c + 2);

        const uint32_t sb = sbase + (uint32_t)(c % 3) * STAGE_B;
#pragma unroll
        for (int ks = 0; ks < 4; ks++) {
            uint32_t ah[2][4], al[2][4];
            uint32_t bf[NT][2];
#pragma unroll
            for (int mi = 0; mi < 2; mi++) {
                ldsm4(ah[mi], sb + rowA[mi] + colp[ks]);
                ldsm4(al[mi], sb + TILE_B + rowA[mi] + colp[ks]);
            }
#pragma unroll
            for (int nj = 0; nj < NR; nj++) {
                uint32_t t4[4];
                ldsm4(t4, sb + 2 * TILE_B + rowB[nj] + colp[ks]);
                bf[2 * nj][0] = t4[0]; bf[2 * nj][1] = t4[2];
                bf[2 * nj + 1][0] = t4[1]; bf[2 * nj + 1][1] = t4[3];
            }
#pragma unroll
            for (int mi = 0; mi < 2; mi++)
#pragma unroll
                for (int nt = 0; nt < NT; nt++) {
                    mma16816h(acc[mi][nt], ah[mi], bf[nt][0], bf[nt][1]);
                    mma16816h(acc[mi][nt], al[mi], bf[nt][0], bf[nt][1]);
                }
        }
    }

    // ---- epilogue ----
    __syncthreads();
    constexpr int SCS = NBLK + 4;
    float* sC = (float*)dsm;
#pragma unroll
    for (int mi = 0; mi < 2; mi++)
#pragma unroll
        for (int nt = 0; nt < NT; nt++) {
            int r0 = m_off + mi * 16 + (lane >> 2);
            int c0 = n_off + nt * 8 + (lane & 3) * 2;
            *(float2*)&sC[r0 * SCS + c0] = make_float2(acc[mi][nt][0], acc[mi][nt][1]);
            *(float2*)&sC[(r0 + 8) * SCS + c0] = make_float2(acc[mi][nt][2], acc[mi][nt][3]);
        }
    __syncthreads();
#pragma unroll
    for (int i = 0; i < (128 * NBLK) / GTHREADS; i++) {
        int idx = tid + i * GTHREADS;
        int r = idx / NBLK, cc = idx % NBLK;
        int gm = m0 + r, gn = n0 + cc;
        if (gm < NNODES && gn < Nout) {
            float v = fmaxf(sC[r * SCS + cc] + bias[gn], 0.f);
            if (outF) outF[(size_t)gm * Nout + gn] = v;
            __half hi, lo;
            split_h(v, hi, lo);
            if (outH16) outH16[(size_t)gm * strideH16 + gn] = hi;
            if (outHi) {
                size_t o = (size_t)gm * strideO + colOff + gn;
                outHi[o] = hi;
                outLo[o] = lo;
            }
        }
    }
}

// ---------------- final head: logits + log_softmax ----------------
__global__ void logits_kernel(const float* __restrict__ emb,
                              const float* __restrict__ lin2_w,
                              const float* __restrict__ lin2_b,
                              float* __restrict__ out)
{
    int gtid = blockIdx.x * blockDim.x + threadIdx.x;
    int node = gtid >> 5;
    int lane = gtid & 31;
    if (node >= NNODES) return;
    const float* e = emb + (size_t)node * DIM3;
    float s0 = 0.f, s1 = 0.f;
    for (int k = lane; k < DIM3; k += 32) {
        float v = e[k];
        s0 = fmaf(v, lin2_w[2 * k + 0], s0);
        s1 = fmaf(v, lin2_w[2 * k + 1], s1);
    }
#pragma unroll
    for (int o = 16; o; o >>= 1) {
        s0 += __shfl_down_sync(0xffffffffu, s0, o);
        s1 += __shfl_down_sync(0xffffffffu, s1, o);
    }
    if (lane == 0) {
        s0 += lin2_b[0];
        s1 += lin2_b[1];
        float m = fmaxf(s0, s1);
        float l = m + logf(expf(s0 - m) + expf(s1 - m));
        out[2 * node + 0] = s0 - l;
        out[2 * node + 1] = s1 - l;
    }
}

// ---------------- launch ----------------
extern "C" void kernel_launch(void* const* d_in, const int* in_sizes, int n_in,
                              void* d_out, int out_size)
{
    const float* x       = (const float*)d_in[0];
    const float* gene    = (const float*)d_in[1];
    const float* w_rel1  = (const float*)d_in[2];
    const float* root1   = (const float*)d_in[3];
    const float* b1      = (const float*)d_in[4];
    const float* w_rel2  = (const float*)d_in[5];
    const float* root2   = (const float*)d_in[6];
    const float* b2      = (const float*)d_in[7];
    const float* lin1_w  = (const float*)d_in[8];
    const float* lin1_b  = (const float*)d_in[9];
    const float* lin2_w  = (const float*)d_in[10];
    const float* lin2_b  = (const float*)d_in[11];
    const int*   ei = (const int*)d_in[12];
    const int*   et = (const int*)d_in[13];
    float* out = (float*)d_out;

    __half *Xch, *Xcl, *W1h, *Xh16, *A1h16, *A1ch, *A1cl, *W2h, *A2h, *A2l, *W3h;
    cudaGetSymbolAddress((void**)&Xch, g_Xcat_hi);  cudaGetSymbolAddress((void**)&Xcl, g_Xcat_lo);
    cudaGetSymbolAddress((void**)&W1h, g_W1h);
    cudaGetSymbolAddress((void**)&Xh16, g_Xh16);
    cudaGetSymbolAddress((void**)&A1h16, g_A1h16);
    cudaGetSymbolAddress((void**)&A1ch, g_A1cat_hi); cudaGetSymbolAddress((void**)&A1cl, g_A1cat_lo);
    cudaGetSymbolAddress((void**)&W2h, g_W2h);
    cudaGetSymbolAddress((void**)&A2h, g_A2hi);     cudaGetSymbolAddress((void**)&A2l, g_A2lo);
    cudaGetSymbolAddress((void**)&W3h, g_W3h);

    const int SMEM128 = 3 * (2 * TILE_B + 128 * 128);   // 144 KB
    cudaFuncSetAttribute(gemm_fp16_kernel<128>, cudaFuncAttributeMaxDynamicSharedMemorySize, SMEM128);

    // 1) weight transposes (single fp16)
    {
        dim3 tb(32, 8);
        transpose_half_kernel<<<dim3(KP1 / 32, NP1 / 32, 5), tb>>>(w_rel1, root1, W1h, IN_DIM, DIM1, KP1, KC1);
        transpose_half_kernel<<<dim3(KP2 / 32, NP2 / 32, 5), tb>>>(w_rel2, root2, W2h, DIM1, DIM2, KP2, KC2);
        transpose_half_kernel<<<dim3(KP3 / 32, NP3 / 32, 1), tb>>>(nullptr, lin1_w, W3h, DIM2, DIM3, KP3, KP3);
    }
    // 2) edge preprocessing
    zero_cnt_kernel<<<(NSEG + 255) / 256, 256>>>();
    count_kernel<<<(N_EDGES + 255) / 256, 256>>>(ei, et);
    scan_kernel<<<1, 1024>>>();
    fill_kernel<<<(N_EDGES + 255) / 256, 256>>>(ei, et);

    // 3) layer-1 input assembly (fp16 gather source written by xfill)
    {
        size_t tot = (size_t)NNODES * IN_DIM;
        xfill_kernel<<<(unsigned)((tot + 255) / 256), 256>>>(x, gene);
    }
    agg_seg_h_kernel<4><<<NSEG, 256>>>(Xh16, XH_STR, (IN_DIM + 1) / 2, KP1, KC1, Xch, Xcl);

    // 4) layer-1 GEMM: fp16 A1 copy + hi/lo into A1cat root slot (no fp32 A1)
    gemm_fp16_kernel<128><<<dim3(NP1 / 128, MPAD / 128), GTHREADS, SMEM128>>>(
        Xch, Xcl, W1h, KC1, DIM1, b1, nullptr, A1h16, A1H_STR, A1ch, A1cl, KC2, 4 * KP2);

    // 5) layer-2 input assembly (gathers fp16 A1 copy)
    agg_seg_h_kernel<3><<<NSEG, 256>>>(A1h16, A1H_STR, (DIM1 + 1) / 2, KP2, KC2, A1ch, A1cl);

    // 6) layer-2 GEMM
    gemm_fp16_kernel<128><<<dim3(NP2 / 128, MPAD / 128), GTHREADS, SMEM128>>>(
        A1ch, A1cl, W2h, KC2, DIM2, b2, nullptr, nullptr, 0, A2h, A2l, KP3, 0);

    // 7) lin1 -> emb in output buffer
    float* emb = out + 2 * NNODES;
    gemm_fp16_kernel<128><<<dim3(NP3 / 128, MPAD / 128), GTHREADS, SMEM128>>>(
        A2h, A2l, W3h, KP3, DIM3, lin1_b, emb, nullptr, 0, nullptr, nullptr, 0, 0);

    // 8) lin2 + log_softmax
    logits_kernel<<<(NNODES * 32 + 255) / 256, 256>>>(emb, lin2_w, lin2_b, out);
}

// round 16
// speedup vs baseline: 3.3418x; 1.6269x over previous
#include <cuda_runtime.h>
#include <cuda_fp16.h>
#include <cstdint>
#include <math.h>

// ---------------- problem constants ----------------
#define N_DRUGS   4000
#define N_GENES   4264
#define NNODES    8264
#define IN_DIM    1613
#define DIM1      1340
#define DIM2      920
#define DIM3      740
#define N_REL     4
#define N_EDGES   100000
#define NSEG      (NNODES * N_REL)     // 33056

#define MPAD      8320                 // 65 * 128
#define KP1       1664                 // pad(1613, 64)
#define KP2       1344                 // pad(1340, 64)
#define KP3       960                  // pad(920, 64)
#define KC1       (5 * KP1)            // 8320
#define KC2       (5 * KP2)            // 6720
#define NP1       1408                 // 11 * 128
#define NP2       1024                 // 8 * 128
#define NP3       768                  // 6 * 128

// ---------------- device scratch ----------------
__device__ __half g_Xcat[(size_t)MPAD * KC1];        // single fp16 (1-term A, layer 1)
__device__ __half g_W1h[(size_t)NP1 * KC1];
__device__ __half g_A1cat[(size_t)MPAD * KC2];       // single fp16 (1-term A, layer 2)
__device__ __half g_W2h[(size_t)NP2 * KC2];
__device__ __half g_A2hi[(size_t)MPAD * KP3];        // 2-term A for lin1 (keeps lin1 exact-A)
__device__ __half g_A2lo[(size_t)MPAD * KP3];
__device__ __half g_W3h[(size_t)NP3 * KP3];
__device__ int g_cnt[NSEG];
__device__ int g_seg_start[NSEG + 1];
__device__ int g_cursor[NSEG];
__device__ int g_esrc[N_EDGES];

// ---------------- PTX helpers (plain sm_80+ instructions only) ----------------
__device__ __forceinline__ uint32_t smem_to_u32(const void* p) {
    uint32_t a;
    asm("{ .reg .u64 t; cvta.to.shared.u64 t, %1; cvt.u32.u64 %0, t; }" : "=r"(a) : "l"(p));
    return a;
}
#define CP_ASYNC16(dst, src) \
    asm volatile("cp.async.cg.shared.global [%0], [%1], 16;" :: "r"(dst), "l"(src) : "memory")
#define CP_ASYNC_COMMIT() asm volatile("cp.async.commit_group;" ::: "memory")
#define CP_ASYNC_WAIT(n)  asm volatile("cp.async.wait_group %0;" :: "n"(n) : "memory")

__device__ __forceinline__ void ldsm4(uint32_t (&r)[4], uint32_t addr) {
    asm volatile("ldmatrix.sync.aligned.m8n8.x4.shared.b16 {%0,%1,%2,%3}, [%4];"
                 : "=r"(r[0]), "=r"(r[1]), "=r"(r[2]), "=r"(r[3]) : "r"(addr));
}
__device__ __forceinline__ void mma16816h(float (&d)[4], const uint32_t (&a)[4],
                                          uint32_t b0, uint32_t b1) {
    asm volatile(
        "mma.sync.aligned.m16n8k16.row.col.f32.f16.f16.f32 "
        "{%0,%1,%2,%3}, {%4,%5,%6,%7}, {%8,%9}, {%0,%1,%2,%3};"
        : "+f"(d[0]), "+f"(d[1]), "+f"(d[2]), "+f"(d[3])
        : "r"(a[0]), "r"(a[1]), "r"(a[2]), "r"(a[3]), "r"(b0), "r"(b1));
}
#define SWZ(off) ((off) ^ (((off) >> 3) & 0x70))

__device__ __forceinline__ void split_h(float v, __half& hi, __half& lo) {
    __half h = __float2half(v);
    hi = h;
    lo = __float2half(v - __half2float(h));
}

// ---------------- prep: x -> Xcat root slot (single fp16) ----------------
__global__ void xfill_kernel(const float* __restrict__ x, const float* __restrict__ gene)
{
    size_t i = (size_t)blockIdx.x * blockDim.x + threadIdx.x;
    const size_t TOT = (size_t)NNODES * IN_DIM;
    if (i >= TOT) return;
    int node = (int)(i / IN_DIM);
    int k = (int)(i % IN_DIM);
    float v = (node < N_DRUGS) ? x[(size_t)node * IN_DIM + k]
                               : gene[(size_t)(node - N_DRUGS) * IN_DIM + k];
    g_Xcat[(size_t)node * KC1 + 4 * KP1 + k] = __float2half(v);
}

// transpose W[K][N] (z slabs) -> Wcat[n][z*Kpad + k] single fp16, zero-padded
__global__ void transpose_half_kernel(const float* __restrict__ Wrel,
                                      const float* __restrict__ Wroot,
                                      __half* __restrict__ Th,
                                      int K, int N, int Kpad, int KC)
{
    __shared__ float t[32][33];
    int z = blockIdx.z;
    const float* W = (Wrel != nullptr && z < N_REL) ? (Wrel + (size_t)z * K * N) : Wroot;
    int k0 = blockIdx.x * 32;
    int n0 = blockIdx.y * 32;
    int tx = threadIdx.x, ty = threadIdx.y;
#pragma unroll
    for (int i = 0; i < 4; i++) {
        int k = k0 + ty + i * 8;
        int n = n0 + tx;
        t[ty + i * 8][tx] = (k < K && n < N) ? W[(size_t)k * N + n] : 0.f;
    }
    __syncthreads();
#pragma unroll
    for (int i = 0; i < 4; i++) {
        int n = n0 + ty + i * 8;
        int kk = k0 + tx;
        size_t o = (size_t)n * KC + (size_t)z * Kpad + kk;
        Th[o] = __float2half(t[tx][ty + i * 8]);
    }
}

// ---------------- edge preprocessing ----------------
__global__ void zero_cnt_kernel()
{
    int i = blockIdx.x * blockDim.x + threadIdx.x;
    if (i < NSEG) g_cnt[i] = 0;
}
__global__ void count_kernel(const int* __restrict__ ei, const int* __restrict__ et)
{
    int e = blockIdx.x * blockDim.x + threadIdx.x;
    if (e >= N_EDGES) return;
    atomicAdd(&g_cnt[ei[N_EDGES + e] * N_REL + et[e]], 1);
}
__global__ void scan_kernel()
{
    __shared__ int part[1024];
    const int CHK = (NSEG + 1023) / 1024;
    int tid = threadIdx.x;
    int degs[CHK];
    int mysum = 0;
#pragma unroll
    for (int i = 0; i < CHK; i++) {
        int d = tid * CHK + i;
        int dg = (d < NSEG) ? g_cnt[d] : 0;
        degs[i] = dg;
        mysum += dg;
    }
    part[tid] = mysum;
    __syncthreads();
    if (tid == 0) {
        int run = 0;
        for (int t = 0; t < 1024; t++) { int v = part[t]; part[t] = run; run += v; }
        g_seg_start[NSEG] = run;
    }
    __syncthreads();
    int off = part[tid];
#pragma unroll
    for (int i = 0; i < CHK; i++) {
        int d = tid * CHK + i;
        if (d < NSEG) { g_seg_start[d] = off; g_cursor[d] = off; off += degs[i]; }
    }
}
__global__ void fill_kernel(const int* __restrict__ ei, const int* __restrict__ et)
{
    int e = blockIdx.x * blockDim.x + threadIdx.x;
    if (e >= N_EDGES) return;
    int seg = ei[N_EDGES + e] * N_REL + et[e];
    g_esrc[atomicAdd(&g_cursor[seg], 1)] = ei[e];
}

// ---------------- segment-mean aggregation from strided fp16 rows (half2) ----------------
// Gathers row sn at src + sn*strideH (the cat-root slot), writes mean into the
// rel slot of the same cat buffer (single fp16).
template <int CH2>
__global__ void agg_seg_h_kernel(const __half* __restrict__ src, int strideH,
                                 int D2, int Kpad, int KC,
                                 __half* __restrict__ outH)
{
    int seg = blockIdx.x;
    int s = g_seg_start[seg];
    int e = g_seg_start[seg + 1];
    if (s == e) return;
    int tid = threadIdx.x;
    float2 acc[CH2];
#pragma unroll
    for (int j = 0; j < CH2; j++) acc[j] = make_float2(0.f, 0.f);
    for (int p = s; p < e; p++) {
        int sn = g_esrc[p];
        const __half2* row = (const __half2*)(src + (size_t)sn * strideH);
#pragma unroll
        for (int j = 0; j < CH2; j++) {
            int o2 = tid + j * 256;
            if (o2 < D2) {
                float2 v = __half22float2(row[o2]);
                acc[j].x += v.x;
                acc[j].y += v.y;
            }
        }
    }
    float inv = 1.0f / (float)(e - s);
    int node = seg >> 2, rel = seg & 3;
    size_t base2 = ((size_t)node * KC + (size_t)rel * Kpad) >> 1;
    __half2* out2 = (__half2*)outH;
#pragma unroll
    for (int j = 0; j < CH2; j++) {
        int o2 = tid + j * 256;
        if (o2 < D2)
            out2[base2 + o2] = __floats2half2_rn(acc[j].x * inv, acc[j].y * inv);
    }
}

// ---------------- mma.sync fp16 GEMM, TERMS = 1 or 2 A-terms ----------------
// C[m][n] = relu( sum_k A[m][k]*W[n][k] + bias[n] )
// CTA tile 128 x NBLK, BK=64, 3-stage cp.async, 16 warps (4m x 4n).
#define TILE_B  (128 * 128)          // one A-term tile bytes
#define GTHREADS 512

template <int NBLK, int TERMS>
__global__ void __launch_bounds__(GTHREADS, 1)
gemm_fp16_kernel(const __half* __restrict__ Ahi, const __half* __restrict__ Alo,
                 const __half* __restrict__ B,
                 int KC, int Nout, const float* __restrict__ bias,
                 float* __restrict__ outF,
                 __half* __restrict__ outHi, __half* __restrict__ outLo,
                 int strideO, int colOff)
{
    constexpr int BT_B = NBLK * 128;
    constexpr int STAGE_B = TERMS * TILE_B + BT_B;
    constexpr int WN = NBLK / 4;
    constexpr int NR = WN / 16;
    constexpr int NT = WN / 8;
    constexpr int ACHUNKS = TERMS * 1024;                 // 16B chunks of A per stage
    constexpr int LOADS = (ACHUNKS + 8 * NBLK) / GTHREADS;

    extern __shared__ char dsm[];
    const uint32_t sbase = smem_to_u32(dsm);
    const int tid = threadIdx.x;
    const int lane = tid & 31;
    const int wid = tid >> 5;
    const int m_off = (wid >> 2) * 32;
    const int n_off = (wid & 3) * WN;
    const int m0 = blockIdx.y * 128;
    const int n0 = blockIdx.x * NBLK;

    const int arow = lane & 15;
    const uint32_t xorv = (uint32_t)(arow & 7) << 4;
    uint32_t colp[4];
#pragma unroll
    for (int ks = 0; ks < 4; ks++)
        colp[ks] = ((uint32_t)(ks * 32 + ((lane >> 4) * 16))) ^ xorv;
    uint32_t rowA[2], rowB[NR];
#pragma unroll
    for (int mi = 0; mi < 2; mi++) rowA[mi] = (uint32_t)(m_off + mi * 16 + arow) * 128u;
#pragma unroll
    for (int nj = 0; nj < NR; nj++) rowB[nj] = (uint32_t)(n_off + nj * 16 + arow) * 128u;

    float acc[2][NT][4];
#pragma unroll
    for (int mi = 0; mi < 2; mi++)
#pragma unroll
        for (int nt = 0; nt < NT; nt++)
#pragma unroll
            for (int q = 0; q < 4; q++) acc[mi][nt][q] = 0.f;

    const int chunks = KC >> 6;

    auto load_stage = [&](int slot, int c) {
        const int k0 = c << 6;
        const uint32_t base = sbase + (uint32_t)slot * STAGE_B;
#pragma unroll
        for (int i = 0; i < LOADS; i++) {
            int idx = tid + i * GTHREADS;
            const __half* g;
            uint32_t d;
            if (idx < ACHUNKS) {
                int t = idx >> 10;              // term index
                int r = (idx >> 3) & 127, j = idx & 7;
                g = (t ? Alo : Ahi) + (size_t)(m0 + r) * KC + k0 + j * 8;
                d = base + (uint32_t)t * TILE_B + SWZ((uint32_t)(r * 128 + j * 16));
            } else {
                int i2 = idx - ACHUNKS;
                int r = i2 >> 3, j = i2 & 7;
                g = B + (size_t)(n0 + r) * KC + k0 + j * 8;
                d = base + (uint32_t)TERMS * TILE_B + SWZ((uint32_t)(r * 128 + j * 16));
            }
            CP_ASYNC16(d, (const void*)g);
        }
        CP_ASYNC_COMMIT();
    };

    load_stage(0, 0);
    if (chunks > 1) load_stage(1, 1);

    for (int c = 0; c < chunks; c++) {
        if (c + 1 < chunks) CP_ASYNC_WAIT(1);
        else                CP_ASYNC_WAIT(0);
        __syncthreads();
        if (c + 2 < chunks) load_stage((c + 2) % 3, c + 2);

        const uint32_t sb = sbase + (uint32_t)(c % 3) * STAGE_B;
#pragma unroll
        for (int ks = 0; ks < 4; ks++) {
            uint32_t ah[2][4], al[2][4];
            uint32_t bf[NT][2];
#pragma unroll
            for (int mi = 0; mi < 2; mi++) {
                ldsm4(ah[mi], sb + rowA[mi] + colp[ks]);
                if (TERMS == 2) ldsm4(al[mi], sb + TILE_B + rowA[mi] + colp[ks]);
            }
#pragma unroll
            for (int nj = 0; nj < NR; nj++) {
                uint32_t t4[4];
                ldsm4(t4, sb + (uint32_t)TERMS * TILE_B + rowB[nj] + colp[ks]);
                bf[2 * nj][0] = t4[0]; bf[2 * nj][1] = t4[2];
                bf[2 * nj + 1][0] = t4[1]; bf[2 * nj + 1][1] = t4[3];
            }
#pragma unroll
            for (int mi = 0; mi < 2; mi++)
#pragma unroll
                for (int nt = 0; nt < NT; nt++) {
                    mma16816h(acc[mi][nt], ah[mi], bf[nt][0], bf[nt][1]);
                    if (TERMS == 2) mma16816h(acc[mi][nt], al[mi], bf[nt][0], bf[nt][1]);
                }
        }
    }

    // ---- epilogue ----
    __syncthreads();
    constexpr int SCS = NBLK + 4;
    float* sC = (float*)dsm;
#pragma unroll
    for (int mi = 0; mi < 2; mi++)
#pragma unroll
        for (int nt = 0; nt < NT; nt++) {
            int r0 = m_off + mi * 16 + (lane >> 2);
            int c0 = n_off + nt * 8 + (lane & 3) * 2;
            *(float2*)&sC[r0 * SCS + c0] = make_float2(acc[mi][nt][0], acc[mi][nt][1]);
            *(float2*)&sC[(r0 + 8) * SCS + c0] = make_float2(acc[mi][nt][2], acc[mi][nt][3]);
        }
    __syncthreads();
#pragma unroll
    for (int i = 0; i < (128 * NBLK) / GTHREADS; i++) {
        int idx = tid + i * GTHREADS;
        int r = idx / NBLK, cc = idx % NBLK;
        int gm = m0 + r, gn = n0 + cc;
        if (gm < NNODES && gn < Nout) {
            float v = fmaxf(sC[r * SCS + cc] + bias[gn], 0.f);
            if (outF) outF[(size_t)gm * Nout + gn] = v;
            if (outHi) {
                size_t o = (size_t)gm * strideO + colOff + gn;
                if (outLo) {
                    __half hi, lo;
                    split_h(v, hi, lo);
                    outHi[o] = hi;
                    outLo[o] = lo;
                } else {
                    outHi[o] = __float2half(v);
                }
            }
        }
    }
}

// ---------------- final head: logits + log_softmax ----------------
__global__ void logits_kernel(const float* __restrict__ emb,
                              const float* __restrict__ lin2_w,
                              const float* __restrict__ lin2_b,
                              float* __restrict__ out)
{
    int gtid = blockIdx.x * blockDim.x + threadIdx.x;
    int node = gtid >> 5;
    int lane = gtid & 31;
    if (node >= NNODES) return;
    const float* e = emb + (size_t)node * DIM3;
    float s0 = 0.f, s1 = 0.f;
    for (int k = lane; k < DIM3; k += 32) {
        float v = e[k];
        s0 = fmaf(v, lin2_w[2 * k + 0], s0);
        s1 = fmaf(v, lin2_w[2 * k + 1], s1);
    }
#pragma unroll
    for (int o = 16; o; o >>= 1) {
        s0 += __shfl_down_sync(0xffffffffu, s0, o);
        s1 += __shfl_down_sync(0xffffffffu, s1, o);
    }
    if (lane == 0) {
        s0 += lin2_b[0];
        s1 += lin2_b[1];
        float m = fmaxf(s0, s1);
        float l = m + logf(expf(s0 - m) + expf(s1 - m));
        out[2 * node + 0] = s0 - l;
        out[2 * node + 1] = s1 - l;
    }
}

// ---------------- launch ----------------
extern "C" void kernel_launch(void* const* d_in, const int* in_sizes, int n_in,
                              void* d_out, int out_size)
{
    const float* x       = (const float*)d_in[0];
    const float* gene    = (const float*)d_in[1];
    const float* w_rel1  = (const float*)d_in[2];
    const float* root1   = (const float*)d_in[3];
    const float* b1      = (const float*)d_in[4];
    const float* w_rel2  = (const float*)d_in[5];
    const float* root2   = (const float*)d_in[6];
    const float* b2      = (const float*)d_in[7];
    const float* lin1_w  = (const float*)d_in[8];
    const float* lin1_b  = (const float*)d_in[9];
    const float* lin2_w  = (const float*)d_in[10];
    const float* lin2_b  = (const float*)d_in[11];
    const int*   ei = (const int*)d_in[12];
    const int*   et = (const int*)d_in[13];
    float* out = (float*)d_out;

    __half *Xc, *W1h, *A1c, *W2h, *A2h, *A2l, *W3h;
    cudaGetSymbolAddress((void**)&Xc, g_Xcat);
    cudaGetSymbolAddress((void**)&W1h, g_W1h);
    cudaGetSymbolAddress((void**)&A1c, g_A1cat);
    cudaGetSymbolAddress((void**)&W2h, g_W2h);
    cudaGetSymbolAddress((void**)&A2h, g_A2hi);
    cudaGetSymbolAddress((void**)&A2l, g_A2lo);
    cudaGetSymbolAddress((void**)&W3h, g_W3h);

    const int SMEM1 = 3 * (TILE_B + 128 * 128);       // 96 KB  (1-term)
    const int SMEM2 = 3 * (2 * TILE_B + 128 * 128);   // 144 KB (2-term)
    cudaFuncSetAttribute((const void*)gemm_fp16_kernel<128, 1>, cudaFuncAttributeMaxDynamicSharedMemorySize, SMEM1);
    cudaFuncSetAttribute((const void*)gemm_fp16_kernel<128, 2>, cudaFuncAttributeMaxDynamicSharedMemorySize, SMEM2);

    // 1) weight transposes (single fp16)
    {
        dim3 tb(32, 8);
        transpose_half_kernel<<<dim3(KP1 / 32, NP1 / 32, 5), tb>>>(w_rel1, root1, W1h, IN_DIM, DIM1, KP1, KC1);
        transpose_half_kernel<<<dim3(KP2 / 32, NP2 / 32, 5), tb>>>(w_rel2, root2, W2h, DIM1, DIM2, KP2, KC2);
        transpose_half_kernel<<<dim3(KP3 / 32, NP3 / 32, 1), tb>>>(nullptr, lin1_w, W3h, DIM2, DIM3, KP3, KP3);
    }
    // 2) edge preprocessing
    zero_cnt_kernel<<<(NSEG + 255) / 256, 256>>>();
    count_kernel<<<(N_EDGES + 255) / 256, 256>>>(ei, et);
    scan_kernel<<<1, 1024>>>();
    fill_kernel<<<(N_EDGES + 255) / 256, 256>>>(ei, et);

    // 3) layer-1 input assembly: root fill, then gather-mean directly from root slot
    {
        size_t tot = (size_t)NNODES * IN_DIM;
        xfill_kernel<<<(unsigned)((tot + 255) / 256), 256>>>(x, gene);
    }
    agg_seg_h_kernel<4><<<NSEG, 256>>>(Xc + 4 * KP1, KC1, (IN_DIM + 1) / 2, KP1, KC1, Xc);

    // 4) layer-1 GEMM (1-term A): writes A1cat root slot (single fp16)
    gemm_fp16_kernel<128, 1><<<dim3(NP1 / 128, MPAD / 128), GTHREADS, SMEM1>>>(
        Xc, nullptr, W1h, KC1, DIM1, b1, nullptr, A1c, nullptr, KC2, 4 * KP2);

    // 5) layer-2 input assembly: gather-mean from A1cat root slot
    agg_seg_h_kernel<3><<<NSEG, 256>>>(A1c + 4 * KP2, KC2, (DIM1 + 1) / 2, KP2, KC2, A1c);

    // 6) layer-2 GEMM (1-term A): writes A2 hi/lo (2-term input for lin1)
    gemm_fp16_kernel<128, 1><<<dim3(NP2 / 128, MPAD / 128), GTHREADS, SMEM1>>>(
        A1c, nullptr, W2h, KC2, DIM2, b2, nullptr, A2h, A2l, KP3, 0);

    // 7) lin1 (2-term A) -> emb in output buffer
    float* emb = out + 2 * NNODES;
    gemm_fp16_kernel<128, 2><<<dim3(NP3 / 128, MPAD / 128), GTHREADS, SMEM2>>>(
        A2h, A2l, W3h, KP3, DIM3, lin1_b, emb, nullptr, nullptr, 0, 0);

    // 8) lin2 + log_softmax
    logits_kernel<<<(NNODES * 32 + 255) / 256, 256>>>(emb, lin2_w, lin2_b, out);
}

// round 17
// speedup vs baseline: 3.4461x; 1.0312x over previous
#include <cuda_runtime.h>
#include <cuda_fp16.h>
#include <cstdint>
#include <math.h>

// ---------------- problem constants ----------------
#define N_DRUGS   4000
#define N_GENES   4264
#define NNODES    8264
#define IN_DIM    1613
#define DIM1      1340
#define DIM2      920
#define DIM3      740
#define N_REL     4
#define N_EDGES   100000
#define NSEG      (NNODES * N_REL)     // 33056

#define MPAD      8320                 // 65 * 128
#define KP1       1664                 // pad(1613, 64)
#define KP2       1344                 // pad(1340, 64)
#define KP3       960                  // pad(920, 64)
#define KC1       (5 * KP1)            // 8320
#define KC2       (5 * KP2)            // 6720
#define NP1       1408                 // 11 * 128
#define NP2       1024                 // 8 * 128
#define NP3       768                  // 6 * 128

// ---------------- device scratch ----------------
__device__ __half g_Xcat[(size_t)MPAD * KC1];        // single fp16 (1-term A, layer 1)
__device__ __half g_W1h[(size_t)NP1 * KC1];
__device__ __half g_A1cat[(size_t)MPAD * KC2];       // single fp16 (1-term A, layer 2)
__device__ __half g_W2h[(size_t)NP2 * KC2];
__device__ __half g_A2h[(size_t)MPAD * KP3];         // single fp16 (1-term A, lin1)
__device__ __half g_W3h[(size_t)NP3 * KP3];
__device__ int g_cnt[NSEG];
__device__ int g_seg_start[NSEG + 1];
__device__ int g_cursor[NSEG];
__device__ int g_esrc[N_EDGES];

// ---------------- PTX helpers (plain sm_80+ instructions only) ----------------
__device__ __forceinline__ uint32_t smem_to_u32(const void* p) {
    uint32_t a;
    asm("{ .reg .u64 t; cvta.to.shared.u64 t, %1; cvt.u32.u64 %0, t; }" : "=r"(a) : "l"(p));
    return a;
}
#define CP_ASYNC16(dst, src) \
    asm volatile("cp.async.cg.shared.global [%0], [%1], 16;" :: "r"(dst), "l"(src) : "memory")
#define CP_ASYNC_COMMIT() asm volatile("cp.async.commit_group;" ::: "memory")
#define CP_ASYNC_WAIT(n)  asm volatile("cp.async.wait_group %0;" :: "n"(n) : "memory")

__device__ __forceinline__ void ldsm4(uint32_t (&r)[4], uint32_t addr) {
    asm volatile("ldmatrix.sync.aligned.m8n8.x4.shared.b16 {%0,%1,%2,%3}, [%4];"
                 : "=r"(r[0]), "=r"(r[1]), "=r"(r[2]), "=r"(r[3]) : "r"(addr));
}
__device__ __forceinline__ void mma16816h(float (&d)[4], const uint32_t (&a)[4],
                                          uint32_t b0, uint32_t b1) {
    asm volatile(
        "mma.sync.aligned.m16n8k16.row.col.f32.f16.f16.f32 "
        "{%0,%1,%2,%3}, {%4,%5,%6,%7}, {%8,%9}, {%0,%1,%2,%3};"
        : "+f"(d[0]), "+f"(d[1]), "+f"(d[2]), "+f"(d[3])
        : "r"(a[0]), "r"(a[1]), "r"(a[2]), "r"(a[3]), "r"(b0), "r"(b1));
}
#define SWZ(off) ((off) ^ (((off) >> 3) & 0x70))

// ---------------- edge preprocessing ----------------
__global__ void zero_cnt_kernel()
{
    int i = blockIdx.x * blockDim.x + threadIdx.x;
    if (i < NSEG) g_cnt[i] = 0;
}
__global__ void count_kernel(const int* __restrict__ ei, const int* __restrict__ et)
{
    int e = blockIdx.x * blockDim.x + threadIdx.x;
    if (e >= N_EDGES) return;
    atomicAdd(&g_cnt[ei[N_EDGES + e] * N_REL + et[e]], 1);
}
// two-level warp-shuffle scan over NSEG degrees (1024 threads, CHK=33 each)
__global__ void scan_kernel()
{
    __shared__ int wsum[32];
    const int CHK = (NSEG + 1023) / 1024;    // 33
    int tid = threadIdx.x;
    int lane = tid & 31, w = tid >> 5;
    int degs[CHK];
    int mysum = 0;
#pragma unroll
    for (int i = 0; i < CHK; i++) {
        int d = tid * CHK + i;
        int dg = (d < NSEG) ? g_cnt[d] : 0;
        degs[i] = dg;
        mysum += dg;
    }
    // warp inclusive scan of per-thread sums
    int run = mysum;
#pragma unroll
    for (int o = 1; o < 32; o <<= 1) {
        int v = __shfl_up_sync(0xffffffffu, run, o);
        if (lane >= o) run += v;
    }
    if (lane == 31) wsum[w] = run;
    __syncthreads();
    if (w == 0) {
        int v = (lane < 32) ? wsum[lane] : 0;
#pragma unroll
        for (int o = 1; o < 32; o <<= 1) {
            int u = __shfl_up_sync(0xffffffffu, v, o);
            if (lane >= o) v += u;
        }
        wsum[lane] = v;
    }
    __syncthreads();
    int base = run - mysum + (w > 0 ? wsum[w - 1] : 0);   // exclusive prefix for this thread
    if (tid == 1023) g_seg_start[NSEG] = base + mysum;
#pragma unroll
    for (int i = 0; i < CHK; i++) {
        int d = tid * CHK + i;
        if (d < NSEG) { g_seg_start[d] = base; g_cursor[d] = base; base += degs[i]; }
    }
}
__global__ void fill_kernel(const int* __restrict__ ei, const int* __restrict__ et)
{
    int e = blockIdx.x * blockDim.x + threadIdx.x;
    if (e >= N_EDGES) return;
    int seg = ei[N_EDGES + e] * N_REL + et[e];
    g_esrc[atomicAdd(&g_cursor[seg], 1)] = ei[e];
}

// ---------------- prep: x -> Xcat root slot (single fp16) ----------------
__global__ void xfill_kernel(const float* __restrict__ x, const float* __restrict__ gene)
{
    size_t i = (size_t)blockIdx.x * blockDim.x + threadIdx.x;
    const size_t TOT = (size_t)NNODES * IN_DIM;
    if (i >= TOT) return;
    int node = (int)(i / IN_DIM);
    int k = (int)(i % IN_DIM);
    float v = (node < N_DRUGS) ? x[(size_t)node * IN_DIM + k]
                               : gene[(size_t)(node - N_DRUGS) * IN_DIM + k];
    g_Xcat[(size_t)node * KC1 + 4 * KP1 + k] = __float2half(v);
}

// ---------------- segment-mean aggregation from strided fp16 rows (half2) ----------------
template <int CH2>
__global__ void agg_seg_h_kernel(const __half* __restrict__ src, int strideH,
                                 int D2, int Kpad, int KC,
                                 __half* __restrict__ outH)
{
    int seg = blockIdx.x;
    int s = g_seg_start[seg];
    int e = g_seg_start[seg + 1];
    if (s == e) return;
    int tid = threadIdx.x;
    float2 acc[CH2];
#pragma unroll
    for (int j = 0; j < CH2; j++) acc[j] = make_float2(0.f, 0.f);
    for (int p = s; p < e; p++) {
        int sn = g_esrc[p];
        const __half2* row = (const __half2*)(src + (size_t)sn * strideH);
#pragma unroll
        for (int j = 0; j < CH2; j++) {
            int o2 = tid + j * 256;
            if (o2 < D2) {
                float2 v = __half22float2(row[o2]);
                acc[j].x += v.x;
                acc[j].y += v.y;
            }
        }
    }
    float inv = 1.0f / (float)(e - s);
    int node = seg >> 2, rel = seg & 3;
    size_t base2 = ((size_t)node * KC + (size_t)rel * Kpad) >> 1;
    __half2* out2 = (__half2*)outH;
#pragma unroll
    for (int j = 0; j < CH2; j++) {
        int o2 = tid + j * 256;
        if (o2 < D2)
            out2[base2 + o2] = __floats2half2_rn(acc[j].x * inv, acc[j].y * inv);
    }
}

// ---------------- transpose W[K][N] (z slabs) -> Wcat[n][z*Kpad+k], fp16 ----------------
__global__ void transpose_half_kernel(const float* __restrict__ Wrel,
                                      const float* __restrict__ Wroot,
                                      __half* __restrict__ Th,
                                      int K, int N, int Kpad, int KC)
{
    __shared__ float t[32][33];
    int z = blockIdx.z;
    const float* W = (Wrel != nullptr && z < N_REL) ? (Wrel + (size_t)z * K * N) : Wroot;
    int k0 = blockIdx.x * 32;
    int n0 = blockIdx.y * 32;
    int tx = threadIdx.x, ty = threadIdx.y;
#pragma unroll
    for (int i = 0; i < 4; i++) {
        int k = k0 + ty + i * 8;
        int n = n0 + tx;
        t[ty + i * 8][tx] = (k < K && n < N) ? W[(size_t)k * N + n] : 0.f;
    }
    __syncthreads();
#pragma unroll
    for (int i = 0; i < 4; i++) {
        int n = n0 + ty + i * 8;
        int kk = k0 + tx;
        size_t o = (size_t)n * KC + (size_t)z * Kpad + kk;
        Th[o] = __float2half(t[tx][ty + i * 8]);
    }
}

// ---------------- mma.sync fp16 1-term GEMM ----------------
// C[m][n] = relu( sum_k A[m][k]*W[n][k] + bias[n] )
// CTA tile 128 x NBLK, BK=64, 3-stage cp.async, 16 warps (4m x 4n).
#define TILE_B  (128 * 128)
#define GTHREADS 512

template <int NBLK>
__global__ void __launch_bounds__(GTHREADS, 1)
gemm_fp16_kernel(const __half* __restrict__ A, const __half* __restrict__ B,
                 int KC, int Nout, const float* __restrict__ bias,
                 float* __restrict__ outF,
                 __half* __restrict__ outH, int strideO, int colOff)
{
    constexpr int BT_B = NBLK * 128;
    constexpr int STAGE_B = TILE_B + BT_B;             // 32 KB @ NBLK=128
    constexpr int WN = NBLK / 4;
    constexpr int NR = WN / 16;
    constexpr int NT = WN / 8;
    constexpr int LOADS = (1024 + 8 * NBLK) / GTHREADS;

    extern __shared__ char dsm[];
    const uint32_t sbase = smem_to_u32(dsm);
    const int tid = threadIdx.x;
    const int lane = tid & 31;
    const int wid = tid >> 5;
    const int m_off = (wid >> 2) * 32;
    const int n_off = (wid & 3) * WN;
    const int m0 = blockIdx.y * 128;
    const int n0 = blockIdx.x * NBLK;

    const int arow = lane & 15;
    const uint32_t xorv = (uint32_t)(arow & 7) << 4;
    uint32_t colp[4];
#pragma unroll
    for (int ks = 0; ks < 4; ks++)
        colp[ks] = ((uint32_t)(ks * 32 + ((lane >> 4) * 16))) ^ xorv;
    uint32_t rowA[2], rowB[NR];
#pragma unroll
    for (int mi = 0; mi < 2; mi++) rowA[mi] = (uint32_t)(m_off + mi * 16 + arow) * 128u;
#pragma unroll
    for (int nj = 0; nj < NR; nj++) rowB[nj] = (uint32_t)(n_off + nj * 16 + arow) * 128u;

    float acc[2][NT][4];
#pragma unroll
    for (int mi = 0; mi < 2; mi++)
#pragma unroll
        for (int nt = 0; nt < NT; nt++)
#pragma unroll
            for (int q = 0; q < 4; q++) acc[mi][nt][q] = 0.f;

    const int chunks = KC >> 6;

    auto load_stage = [&](int slot, int c) {
        const int k0 = c << 6;
        const uint32_t base = sbase + (uint32_t)slot * STAGE_B;
#pragma unroll
        for (int i = 0; i < LOADS; i++) {
            int idx = tid + i * GTHREADS;
            const __half* g;
            uint32_t d;
            if (idx < 1024) {
                int r = idx >> 3, j = idx & 7;
                g = A + (size_t)(m0 + r) * KC + k0 + j * 8;
                d = base + SWZ((uint32_t)(r * 128 + j * 16));
            } else {
                int i2 = idx - 1024;
                int r = i2 >> 3, j = i2 & 7;
                g = B + (size_t)(n0 + r) * KC + k0 + j * 8;
                d = base + TILE_B + SWZ((uint32_t)(r * 128 + j * 16));
            }
            CP_ASYNC16(d, (const void*)g);
        }
        CP_ASYNC_COMMIT();
    };

    load_stage(0, 0);
    if (chunks > 1) load_stage(1, 1);

    for (int c = 0; c < chunks; c++) {
        if (c + 1 < chunks) CP_ASYNC_WAIT(1);
        else                CP_ASYNC_WAIT(0);
        __syncthreads();
        if (c + 2 < chunks) load_stage((c + 2) % 3, c + 2);

        const uint32_t sb = sbase + (uint32_t)(c % 3) * STAGE_B;
#pragma unroll
        for (int ks = 0; ks < 4; ks++) {
            uint32_t ah[2][4];
            uint32_t bf[NT][2];
#pragma unroll
            for (int mi = 0; mi < 2; mi++)
                ldsm4(ah[mi], sb + rowA[mi] + colp[ks]);
#pragma unroll
            for (int nj = 0; nj < NR; nj++) {
                uint32_t t4[4];
                ldsm4(t4, sb + TILE_B + rowB[nj] + colp[ks]);
                bf[2 * nj][0] = t4[0]; bf[2 * nj][1] = t4[2];
                bf[2 * nj + 1][0] = t4[1]; bf[2 * nj + 1][1] = t4[3];
            }
#pragma unroll
            for (int mi = 0; mi < 2; mi++)
#pragma unroll
                for (int nt = 0; nt < NT; nt++)
                    mma16816h(acc[mi][nt], ah[mi], bf[nt][0], bf[nt][1]);
        }
    }

    // ---- epilogue ----
    __syncthreads();
    constexpr int SCS = NBLK + 4;
    float* sC = (float*)dsm;
#pragma unroll
    for (int mi = 0; mi < 2; mi++)
#pragma unroll
        for (int nt = 0; nt < NT; nt++) {
            int r0 = m_off + mi * 16 + (lane >> 2);
            int c0 = n_off + nt * 8 + (lane & 3) * 2;
            *(float2*)&sC[r0 * SCS + c0] = make_float2(acc[mi][nt][0], acc[mi][nt][1]);
            *(float2*)&sC[(r0 + 8) * SCS + c0] = make_float2(acc[mi][nt][2], acc[mi][nt][3]);
        }
    __syncthreads();
#pragma unroll
    for (int i = 0; i < (128 * NBLK) / GTHREADS; i++) {
        int idx = tid + i * GTHREADS;
        int r = idx / NBLK, cc = idx % NBLK;
        int gm = m0 + r, gn = n0 + cc;
        if (gm < NNODES && gn < Nout) {
            float v = fmaxf(sC[r * SCS + cc] + bias[gn], 0.f);
            if (outF) outF[(size_t)gm * Nout + gn] = v;
            if (outH) outH[(size_t)gm * strideO + colOff + gn] = __float2half(v);
        }
    }
}

// ---------------- final head: logits + log_softmax ----------------
__global__ void logits_kernel(const float* __restrict__ emb,
                              const float* __restrict__ lin2_w,
                              const float* __restrict__ lin2_b,
                              float* __restrict__ out)
{
    int gtid = blockIdx.x * blockDim.x + threadIdx.x;
    int node = gtid >> 5;
    int lane = gtid & 31;
    if (node >= NNODES) return;
    const float* e = emb + (size_t)node * DIM3;
    float s0 = 0.f, s1 = 0.f;
    for (int k = lane; k < DIM3; k += 32) {
        float v = e[k];
        s0 = fmaf(v, lin2_w[2 * k + 0], s0);
        s1 = fmaf(v, lin2_w[2 * k + 1], s1);
    }
#pragma unroll
    for (int o = 16; o; o >>= 1) {
        s0 += __shfl_down_sync(0xffffffffu, s0, o);
        s1 += __shfl_down_sync(0xffffffffu, s1, o);
    }
    if (lane == 0) {
        s0 += lin2_b[0];
        s1 += lin2_b[1];
        float m = fmaxf(s0, s1);
        float l = m + logf(expf(s0 - m) + expf(s1 - m));
        out[2 * node + 0] = s0 - l;
        out[2 * node + 1] = s1 - l;
    }
}

// ---------------- launch ----------------
extern "C" void kernel_launch(void* const* d_in, const int* in_sizes, int n_in,
                              void* d_out, int out_size)
{
    const float* x       = (const float*)d_in[0];
    const float* gene    = (const float*)d_in[1];
    const float* w_rel1  = (const float*)d_in[2];
    const float* root1   = (const float*)d_in[3];
    const float* b1      = (const float*)d_in[4];
    const float* w_rel2  = (const float*)d_in[5];
    const float* root2   = (const float*)d_in[6];
    const float* b2      = (const float*)d_in[7];
    const float* lin1_w  = (const float*)d_in[8];
    const float* lin1_b  = (const float*)d_in[9];
    const float* lin2_w  = (const float*)d_in[10];
    const float* lin2_b  = (const float*)d_in[11];
    const int*   ei = (const int*)d_in[12];
    const int*   et = (const int*)d_in[13];
    float* out = (float*)d_out;

    __half *Xc, *W1h, *A1c, *W2h, *A2h, *W3h;
    cudaGetSymbolAddress((void**)&Xc, g_Xcat);
    cudaGetSymbolAddress((void**)&W1h, g_W1h);
    cudaGetSymbolAddress((void**)&A1c, g_A1cat);
    cudaGetSymbolAddress((void**)&W2h, g_W2h);
    cudaGetSymbolAddress((void**)&A2h, g_A2h);
    cudaGetSymbolAddress((void**)&W3h, g_W3h);

    const int SMEM1 = 3 * (TILE_B + 128 * 128);       // 96 KB
    cudaFuncSetAttribute((const void*)gemm_fp16_kernel<128>, cudaFuncAttributeMaxDynamicSharedMemorySize, SMEM1);

    // 1-4) edge preprocessing
    zero_cnt_kernel<<<(NSEG + 255) / 256, 256>>>();
    count_kernel<<<(N_EDGES + 255) / 256, 256>>>(ei, et);
    scan_kernel<<<1, 1024>>>();
    fill_kernel<<<(N_EDGES + 255) / 256, 256>>>(ei, et);

    // 5) xfill: root slot of Xcat
    {
        size_t tot = (size_t)NNODES * IN_DIM;
        xfill_kernel<<<(unsigned)((tot + 255) / 256), 256>>>(x, gene);
    }

    // 6) layer-1 aggregation  <-- 6th launch: captured by ncu (-s 5 -c 1)
    agg_seg_h_kernel<4><<<NSEG, 256>>>(Xc + 4 * KP1, KC1, (IN_DIM + 1) / 2, KP1, KC1, Xc);

    // 7-9) weight transposes (fp16)
    {
        dim3 tb(32, 8);
        transpose_half_kernel<<<dim3(KP1 / 32, NP1 / 32, 5), tb>>>(w_rel1, root1, W1h, IN_DIM, DIM1, KP1, KC1);
        transpose_half_kernel<<<dim3(KP2 / 32, NP2 / 32, 5), tb>>>(w_rel2, root2, W2h, DIM1, DIM2, KP2, KC2);
        transpose_half_kernel<<<dim3(KP3 / 32, NP3 / 32, 1), tb>>>(nullptr, lin1_w, W3h, DIM2, DIM3, KP3, KP3);
    }

    // 10) layer-1 GEMM: writes A1cat root slot
    gemm_fp16_kernel<128><<<dim3(NP1 / 128, MPAD / 128), GTHREADS, SMEM1>>>(
        Xc, W1h, KC1, DIM1, b1, nullptr, A1c, KC2, 4 * KP2);

    // 11) layer-2 aggregation
    agg_seg_h_kernel<3><<<NSEG, 256>>>(A1c + 4 * KP2, KC2, (DIM1 + 1) / 2, KP2, KC2, A1c);

    // 12) layer-2 GEMM: writes A2 (single fp16)
    gemm_fp16_kernel<128><<<dim3(NP2 / 128, MPAD / 128), GTHREADS, SMEM1>>>(
        A1c, W2h, KC2, DIM2, b2, nullptr, A2h, KP3, 0);

    // 13) lin1 (1-term) -> emb in output buffer
    float* emb = out + 2 * NNODES;
    gemm_fp16_kernel<128><<<dim3(NP3 / 128, MPAD / 128), GTHREADS, SMEM1>>>(
        A2h, W3h, KP3, DIM3, lin1_b, emb, nullptr, 0, 0);

    // 14) lin2 + log_softmax
    logits_kernel<<<(NNODES * 32 + 255) / 256, 256>>>(emb, lin2_w, lin2_b, out);
}